// round 9
// baseline (speedup 1.0000x reference)
#include <cuda_runtime.h>
#include <cuda_bf16.h>
#include <cuda_fp16.h>
#include <math.h>
#include <stdint.h>

#define Bn 256
#define Sn 141
#define Vn 1000
#define En 256
#define Hn 512
#define G4 2048   // 4*H
#define VP 1024   // padded vocab

#define NC_STEP 128         // recurrence CTAs (4 groups of 32)
#define NCTA    148         // persistent CTAs (1/SM)
#define NOUT    (Sn * 32)   // out tiles: per t, 2 m-tiles x 16 n-tiles

// ---------------- device scratch ----------------
__device__ float d_embgateP[(size_t)Vn * G4];     // [v][jp] fp32
__device__ float d_encgateP[(size_t)Bn * G4];     // [b][jp] fp32
__device__ __half d_Whh_h[(size_t)G4 * Hn];       // [jp][k] fp16 hi
__device__ __half d_Whh_l[(size_t)G4 * Hn];       // [jp][k] fp16 lo * 2^12
__device__ __half d_outW_h[(size_t)VP * Hn];      // [v][k] fp16
__device__ __half d_hs_f16[(size_t)Sn * Bn * Hn]; // [t][b][k] fp16

// sync state: d_arrive[mi*32+nblk] = t+1 once CTA finished step t (monotonic).
__device__ unsigned d_arrive[128];
__device__ unsigned d_wq;

__device__ __forceinline__ int jperm(int j) {
  return ((j & 511) >> 4) * 64 + (j >> 9) * 16 + (j & 15);
}

// ---------------- PTX helpers (plain sm_80+ only) ----------------
__device__ __forceinline__ void cp16(uint32_t dst, const void* src) {
  asm volatile("cp.async.cg.shared.global [%0], [%1], 16;" :: "r"(dst), "l"(src));
}
__device__ __forceinline__ void cp_commit() { asm volatile("cp.async.commit_group;"); }
__device__ __forceinline__ void cp_wait0() { asm volatile("cp.async.wait_group 0;" ::: "memory"); }
__device__ __forceinline__ void cp_wait1() { asm volatile("cp.async.wait_group 1;" ::: "memory"); }
__device__ __forceinline__ void cp_wait2() { asm volatile("cp.async.wait_group 2;" ::: "memory"); }

__device__ __forceinline__ void ldm4(uint32_t& r0, uint32_t& r1, uint32_t& r2, uint32_t& r3,
                                     uint32_t addr) {
  asm volatile("ldmatrix.sync.aligned.m8n8.x4.shared.b16 {%0,%1,%2,%3}, [%4];"
               : "=r"(r0), "=r"(r1), "=r"(r2), "=r"(r3) : "r"(addr));
}
__device__ __forceinline__ void mma_f16(float* d, const uint32_t* a, uint32_t b0, uint32_t b1) {
  asm volatile(
    "mma.sync.aligned.m16n8k16.row.col.f32.f16.f16.f32 "
    "{%0,%1,%2,%3}, {%4,%5,%6,%7}, {%8,%9}, {%0,%1,%2,%3};"
    : "+f"(d[0]), "+f"(d[1]), "+f"(d[2]), "+f"(d[3])
    : "r"(a[0]), "r"(a[1]), "r"(a[2]), "r"(a[3]), "r"(b0), "r"(b1));
}
__device__ __forceinline__ unsigned ld_acq(unsigned* p) {
  unsigned v;
  asm volatile("ld.acquire.gpu.u32 %0, [%1];" : "=r"(v) : "l"(p) : "memory");
  return v;
}
__device__ __forceinline__ void st_rel(unsigned* p, unsigned v) {
  asm volatile("st.release.gpu.u32 [%0], %1;" :: "l"(p), "r"(v) : "memory");
}

// ---------------- smem layout (recurrence) ----------------
#define BH_RES   0                     // 65536
#define BL_RES   65536                 // 65536
#define A_BUFS   131072                // 4 x 8192
#define ADD_EMB  163840                // [64][64] f32
#define ADD_ENC  180224
#define GS_OFF   196608                // [64][68] f32
#define GS_STRIDE 68
#define FUSED_SMEM 214016
// Out path (reuses offset 0): A fp16 128 rows + B 64 rows per buffer (24K)
#define STG_O    24576
#define OA_OFF   0
#define OB_HI    16384

// ---------------------------------------------------------------------------
// Merged prep kernel
// ---------------------------------------------------------------------------
#define MMA16(As, Bs) do {                                                       \
    _Pragma("unroll")                                                            \
    for (int kk = 0; kk < 16; ++kk) {                                            \
      float4 a = *(const float4*)&As[kk][ty * 4];                                \
      float4 b = *(const float4*)&Bs[kk][tx * 4];                                \
      acc[0][0] += a.x*b.x; acc[0][1] += a.x*b.y; acc[0][2] += a.x*b.z; acc[0][3] += a.x*b.w; \
      acc[1][0] += a.y*b.x; acc[1][1] += a.y*b.y; acc[1][2] += a.y*b.z; acc[1][3] += a.y*b.w; \
      acc[2][0] += a.z*b.x; acc[2][1] += a.z*b.y; acc[2][2] += a.z*b.z; acc[2][3] += a.z*b.w; \
      acc[3][0] += a.w*b.x; acc[3][1] += a.w*b.y; acc[3][2] += a.w*b.z; acc[3][3] += a.w*b.w; \
    } } while (0)

__global__ __launch_bounds__(256) void prep_all(
    const float* __restrict__ enc, const float* __restrict__ emb,
    const float* __restrict__ Wih, const float* __restrict__ Whh,
    const float* __restrict__ bih, const float* __restrict__ bhh,
    const float* __restrict__ outW) {
  __shared__ float As[16][64];
  __shared__ float Bs[16][64];
  int bid = blockIdx.x;
  int tid = threadIdx.x;

  if (bid < 640) {
    bool is_emb = bid < 512;
    int m0, n0;
    if (is_emb) { m0 = (bid & 15) * 64; n0 = (bid >> 4) * 64; }
    else        { int b2 = bid - 512; m0 = (b2 & 3) * 64; n0 = (b2 >> 2) * 64; }
    int tx = tid & 15, ty = tid >> 4;
    int lr = tid >> 2, lq = tid & 3;
    float acc[4][4] = {};
    for (int kc = 0; kc < En; kc += 16) {
      float4 av = make_float4(0.f, 0.f, 0.f, 0.f);
      float4 bv;
      if (is_emb) {
        if (m0 + lr < Vn)
          av = *(const float4*)(emb + (size_t)(m0 + lr) * En + kc + lq * 4);
        bv = *(const float4*)(Wih + (size_t)(n0 + lr) * (2 * En) + kc + lq * 4);
      } else {
        av = *(const float4*)(enc + (size_t)(m0 + lr) * En + kc + lq * 4);
        bv = *(const float4*)(Wih + (size_t)(n0 + lr) * (2 * En) + En + kc + lq * 4);
      }
      __syncthreads();
      As[lq*4+0][lr] = av.x; As[lq*4+1][lr] = av.y; As[lq*4+2][lr] = av.z; As[lq*4+3][lr] = av.w;
      Bs[lq*4+0][lr] = bv.x; Bs[lq*4+1][lr] = bv.y; Bs[lq*4+2][lr] = bv.z; Bs[lq*4+3][lr] = bv.w;
      __syncthreads();
      MMA16(As, Bs);
    }
#pragma unroll
    for (int ii = 0; ii < 4; ++ii) {
      int m = m0 + ty * 4 + ii;
      if (is_emb && m >= Vn) continue;
#pragma unroll
      for (int jj = 0; jj < 4; ++jj) {
        int n = n0 + tx * 4 + jj;
        if (is_emb)
          d_embgateP[(size_t)m * G4 + jperm(n)] = acc[ii][jj];
        else
          d_encgateP[(size_t)m * G4 + jperm(n)] = acc[ii][jj] + bih[n] + bhh[n];
      }
    }
  } else if (bid < 1664) {
    int i = (bid - 640) * 256 + tid;
    int e0 = i * 4;
    int j = e0 >> 9, k0 = e0 & 511;
    int jp = jperm(j);
    float4 x = *(const float4*)(Whh + e0);
    __half h[4], l[4];
    float xs[4] = {x.x, x.y, x.z, x.w};
#pragma unroll
    for (int q = 0; q < 4; ++q) {
      h[q] = __float2half_rn(xs[q]);
      l[q] = __float2half_rn((xs[q] - __half2float(h[q])) * 4096.f);
    }
    *(uint2*)(d_Whh_h + (size_t)jp * Hn + k0) = *(const uint2*)h;
    *(uint2*)(d_Whh_l + (size_t)jp * Hn + k0) = *(const uint2*)l;
  } else if (bid < 2176) {
    int i = (bid - 1664) * 256 + tid;
    int e0 = i * 4;
    int v = e0 >> 9;
    __half h[4];
    if (v < Vn) {
      float4 x = *(const float4*)(outW + e0);
      h[0] = __float2half_rn(x.x); h[1] = __float2half_rn(x.y);
      h[2] = __float2half_rn(x.z); h[3] = __float2half_rn(x.w);
    } else {
#pragma unroll
      for (int q = 0; q < 4; ++q) h[q] = __float2half_rn(0.f);
    }
    *(uint2*)(d_outW_h + e0) = *(const uint2*)h;
  } else {
    if (tid < 128) d_arrive[tid] = 0;
    if (tid == 0) d_wq = 0;
  }
}

// ============================================================================
// Recurrence: CTA tile 64x64, warp tile 16x32 (8 warps). B resident in smem.
// ============================================================================
#define LOADA_R(c, buf, AP)  do {                                                \
    int kc = (c) * 64;                                                           \
    uint32_t st = su + A_BUFS + (buf) * 8192;                                    \
    int row = tid >> 2;                                                          \
    int sg0 = (tid & 3) * 2;                                                     \
    uint32_t sw = (uint32_t)(row & 7) * 16;                                      \
    _Pragma("unroll")                                                            \
    for (int q = 0; q < 2; ++q) {                                                \
      int sg = sg0 + q;                                                          \
      uint32_t so = (uint32_t)row * 128 + (((uint32_t)(sg * 16)) ^ sw);          \
      cp16(st + so, (AP) + (size_t)row * Hn + kc + sg * 8);                      \
    }                                                                            \
    cp_commit();                                                                 \
  } while (0)

__device__ __forceinline__ void compute_chunk_r(
    float accH[4][4], float accL[4][4], uint32_t abase,
    uint32_t bhbase, uint32_t blbase, int wm, int wn, int lane) {
  int lr = lane & 7;
  int sel = lane >> 3;
  int a_roff = (sel & 1) * 8;
  int a_koff = (sel & 2) * 8;
  int b_koff = (sel & 1) * 16;
  int b_roff = (sel & 2) * 4;
  uint32_t swm = (uint32_t)(lr * 16);

#pragma unroll
  for (int ks = 0; ks < 4; ++ks) {
    int kb = ks * 32;
    uint32_t a[4], bh[2][4], bl[2][4];
    {
      int row = wm * 16 + lr + a_roff;
      uint32_t off = (uint32_t)row * 128 + (((uint32_t)(kb + a_koff)) ^ swm);
      ldm4(a[0], a[1], a[2], a[3], abase + off);
    }
#pragma unroll
    for (int p = 0; p < 2; ++p) {
      int row = wn * 32 + p * 16 + lr + b_roff;
      uint32_t off = (uint32_t)row * 128 + (((uint32_t)(kb + b_koff)) ^ swm);
      ldm4(bh[p][0], bh[p][1], bh[p][2], bh[p][3], bhbase + off);
      ldm4(bl[p][0], bl[p][1], bl[p][2], bl[p][3], blbase + off);
    }
#pragma unroll
    for (int nt = 0; nt < 4; ++nt) {
      int p = nt >> 1, q = (nt & 1) * 2;
      mma_f16(accH[nt], a, bh[p][q], bh[p][q + 1]);
      mma_f16(accL[nt], a, bl[p][q], bl[p][q + 1]);
    }
  }
}

// ============================================================================
// Out tile: CTA tile 128x64, warp tile 32x32, single fp16 chain, 2-deep bufs.
// ============================================================================
#define LOADC_O(c, buf, AP, BhP)  do {                                           \
    int kc = (c) * 64;                                                           \
    uint32_t st = su + (buf) * STG_O;                                            \
    {                                                                            \
      int rowA = tid >> 1;                                                       \
      int sg0 = (tid & 1) * 4;                                                   \
      uint32_t swA = (uint32_t)(rowA & 7) * 16;                                  \
      _Pragma("unroll")                                                          \
      for (int q = 0; q < 4; ++q) {                                              \
        int sg = sg0 + q;                                                        \
        uint32_t so = (uint32_t)rowA * 128 + (((uint32_t)(sg * 16)) ^ swA);      \
        cp16(st + OA_OFF + so, (AP) + (size_t)rowA * Hn + kc + sg * 8);          \
      }                                                                          \
    }                                                                            \
    {                                                                            \
      int rB = tid >> 2;                                                         \
      int sg0 = (tid & 3) * 2;                                                   \
      uint32_t swB = (uint32_t)(rB & 7) * 16;                                    \
      _Pragma("unroll")                                                          \
      for (int q = 0; q < 2; ++q) {                                              \
        int sg = sg0 + q;                                                        \
        uint32_t so = (uint32_t)rB * 128 + (((uint32_t)(sg * 16)) ^ swB);        \
        cp16(st + OB_HI + so, (BhP) + (size_t)rB * Hn + kc + sg * 8);            \
      }                                                                          \
    }                                                                            \
    cp_commit();                                                                 \
  } while (0)

__device__ __forceinline__ void compute_chunk_o(
    float accH[2][4][4], uint32_t su, int buf, int wm, int wn, int lane) {
  uint32_t base = su + buf * STG_O;
  int lr = lane & 7;
  int sel = lane >> 3;
  int a_roff = (sel & 1) * 8;
  int a_koff = (sel & 2) * 8;
  int b_koff = (sel & 1) * 16;
  int b_roff = (sel & 2) * 4;
  uint32_t swm = (uint32_t)(lr * 16);

#pragma unroll
  for (int ks = 0; ks < 4; ++ks) {
    int kb = ks * 32;
    uint32_t a[2][4], bh[2][4];
#pragma unroll
    for (int i = 0; i < 2; ++i) {
      int row = wm * 32 + i * 16 + lr + a_roff;
      uint32_t off = (uint32_t)row * 128 + (((uint32_t)(kb + a_koff)) ^ swm);
      ldm4(a[i][0], a[i][1], a[i][2], a[i][3], base + OA_OFF + off);
    }
#pragma unroll
    for (int p = 0; p < 2; ++p) {
      int row = wn * 32 + p * 16 + lr + b_roff;
      uint32_t off = (uint32_t)row * 128 + (((uint32_t)(kb + b_koff)) ^ swm);
      ldm4(bh[p][0], bh[p][1], bh[p][2], bh[p][3], base + OB_HI + off);
    }
#pragma unroll
    for (int i = 0; i < 2; ++i) {
#pragma unroll
      for (int nt = 0; nt < 4; ++nt) {
        int p = nt >> 1, q = (nt & 1) * 2;
        mma_f16(accH[i][nt], a[i], bh[p][q], bh[p][q + 1]);
      }
    }
  }
}

// ---------------------------------------------------------------------------
// Persistent fused kernel.
// ---------------------------------------------------------------------------
__global__ __launch_bounds__(256, 1) void fused_kernel(
    const int* __restrict__ tgt, const float* __restrict__ outb,
    float* __restrict__ out) {
  extern __shared__ __align__(1024) char smem[];
  __shared__ unsigned sidx;
  uint32_t su = (uint32_t)__cvta_generic_to_shared(smem);
  int tid = threadIdx.x;
  int lane = tid & 31, wid = tid >> 5;
  int wm = wid >> 1, wn = wid & 1;

  if (blockIdx.x < NC_STEP) {
    // ========== recurrence: CTA tile 64 b-rows x 64 jp-cols ==========
    int mi = blockIdx.x >> 5, nblk = blockIdx.x & 31;
    int m0 = mi * 64, n0 = nblk * 64;

    // ---- resident loads: B (Whh tile) + enc addend ----
    {
      const __half* Bh = d_Whh_h + (size_t)n0 * Hn;
      const __half* Bl = d_Whh_l + (size_t)n0 * Hn;
      int row = tid >> 2;
      int sg0 = (tid & 3) * 2;
      uint32_t sw = (uint32_t)(row & 7) * 16;
#pragma unroll
      for (int c = 0; c < 8; ++c) {
#pragma unroll
        for (int q = 0; q < 2; ++q) {
          int sg = sg0 + q;
          uint32_t so = (uint32_t)row * 128 + (((uint32_t)(sg * 16)) ^ sw);
          cp16(su + BH_RES + c * 8192 + so, Bh + (size_t)row * Hn + c * 64 + sg * 8);
          cp16(su + BL_RES + c * 8192 + so, Bl + (size_t)row * Hn + c * 64 + sg * 8);
        }
      }
      int r = tid >> 2, sg0e = (tid & 3) * 4;
      const float* sc = d_encgateP + (size_t)(m0 + r) * G4 + n0;
      uint32_t dc = su + ADD_ENC + r * 256;
#pragma unroll
      for (int q = 0; q < 4; ++q)
        cp16(dc + (sg0e + q) * 16, sc + (sg0e + q) * 4);
      cp_commit();
      cp_wait0();
    }
    __syncthreads();

    int em_r = tid >> 2, em_sg = (tid & 3) * 4;
    int ep_m = tid >> 2, ep_k0 = (tid & 3) * 4;
    int ep_b = m0 + ep_m;
    int ep_kbase = nblk * 16 + ep_k0;
    const float* aE = (const float*)(smem + ADD_EMB) + ep_m * 64;
    const float* aC = (const float*)(smem + ADD_ENC) + ep_m * 64;
    float cpv[4] = {0.f, 0.f, 0.f, 0.f};

    for (int t = 0; t < Sn; ++t) {
      // emb addend for this step
      {
        int tok = tgt[(size_t)(m0 + em_r) * Sn + t];
        const float* se = d_embgateP + (size_t)tok * G4 + n0;
        uint32_t de = su + ADD_EMB + em_r * 256;
#pragma unroll
        for (int q = 0; q < 4; ++q)
          cp16(de + (em_sg + q) * 16, se + (em_sg + q) * 4);
        cp_commit();
      }

      if (t > 0) {
        float accH[4][4] = {};
        float accL[4][4] = {};
        const __half* A = d_hs_f16 + ((size_t)(t - 1) * Bn + m0) * Hn;
        LOADA_R(0, 0, A);
        LOADA_R(1, 1, A);
        LOADA_R(2, 2, A);
#pragma unroll 1
        for (int c = 0; c < 8; ++c) {
          if (c <= 5) cp_wait2();
          else if (c == 6) cp_wait1();
          else cp_wait0();
          __syncthreads();
          compute_chunk_r(accH, accL,
                          su + A_BUFS + (c & 3) * 8192,
                          su + BH_RES + c * 8192,
                          su + BL_RES + c * 8192, wm, wn, lane);
          if (c + 3 < 8) LOADA_R(c + 3, (c + 3) & 3, A);
        }
        __syncthreads();
        float* Gs = (float*)(smem + GS_OFF);
        int r0 = (lane >> 2), c0 = (lane & 3) * 2;
        const float kinv = 1.f / 4096.f;
#pragma unroll
        for (int nt = 0; nt < 4; ++nt) {
          int row = wm * 16 + r0;
          int col = wn * 32 + nt * 8 + c0;
          Gs[row * GS_STRIDE + col]           = accH[nt][0] + accL[nt][0] * kinv;
          Gs[row * GS_STRIDE + col + 1]       = accH[nt][1] + accL[nt][1] * kinv;
          Gs[(row + 8) * GS_STRIDE + col]     = accH[nt][2] + accL[nt][2] * kinv;
          Gs[(row + 8) * GS_STRIDE + col + 1] = accH[nt][3] + accL[nt][3] * kinv;
        }
      } else {
        cp_wait0();
      }
      __syncthreads();

      // ---- fused LSTM elementwise: 4 cells/thread ----
      const float* Gs = (const float*)(smem + GS_OFF);
      __half hf[4];
#pragma unroll
      for (int q = 0; q < 4; ++q) {
        int kk = ep_k0 + q;
        float gi = aE[kk]      + aC[kk];
        float gf = aE[16 + kk] + aC[16 + kk];
        float gg = aE[32 + kk] + aC[32 + kk];
        float go = aE[48 + kk] + aC[48 + kk];
        if (t > 0) {
          gi += Gs[ep_m * GS_STRIDE + kk];
          gf += Gs[ep_m * GS_STRIDE + 16 + kk];
          gg += Gs[ep_m * GS_STRIDE + 32 + kk];
          go += Gs[ep_m * GS_STRIDE + 48 + kk];
        }
        float iv = 1.f / (1.f + expf(-gi));
        float fv = 1.f / (1.f + expf(-gf));
        float gv = tanhf(gg);
        float ov = 1.f / (1.f + expf(-go));
        float cc = fv * cpv[q] + iv * gv;
        cpv[q] = cc;
        hf[q] = __float2half_rn(ov * tanhf(cc));
      }
      *(uint2*)(d_hs_f16 + ((size_t)t * Bn + ep_b) * Hn + ep_kbase) = *(const uint2*)hf;

      // ---- distributed per-group barrier ----
      __threadfence();
      __syncthreads();
      if (tid == 0) st_rel(&d_arrive[blockIdx.x], (unsigned)(t + 1));
      if (tid < 32) {
        while (!__all_sync(0xffffffffu,
                           ld_acq(&d_arrive[mi * 32 + tid]) >= (unsigned)(t + 1))) { }
      }
      __syncthreads();
    }
  }

  // ========== out-GEMM worker pool (all CTAs) ==========
  for (;;) {
    __syncthreads();
    if (tid == 0) sidx = atomicAdd(&d_wq, 1);
    __syncthreads();
    unsigned idx = sidx;
    if (idx >= NOUT) break;
    int t = idx >> 5;
    int sub = idx & 31;
    int mtile = sub >> 4;
    int m0g = t * Bn + mtile * 128;
    int n0 = (sub & 15) * 64;

    // wait for the 64 producer CTAs covering rows [mtile*128, +128)
    for (;;) {
      bool ok = true;
      if (tid < 64) ok = (ld_acq(&d_arrive[mtile * 64 + tid]) >= (unsigned)(t + 1));
      if (__syncthreads_and(ok)) break;
      __nanosleep(64);
    }

    const __half* A  = d_hs_f16 + (size_t)m0g * Hn;
    const __half* Bh = d_outW_h + (size_t)n0 * Hn;

    float accH[2][4][4] = {};
    LOADC_O(0, 0, A, Bh);
    LOADC_O(1, 1, A, Bh);
#pragma unroll 1
    for (int c = 0; c < 8; ++c) {
      if (c < 7) cp_wait1(); else cp_wait0();
      __syncthreads();
      compute_chunk_o(accH, su, c & 1, wm, wn, lane);
      __syncthreads();
      if (c + 2 < 8) LOADC_O(c + 2, c & 1, A, Bh);
    }

    int r0 = lane >> 2, c0 = (lane & 3) * 2;
#pragma unroll
    for (int nt = 0; nt < 4; ++nt) {
      int v = n0 + wn * 32 + nt * 8 + c0;
      if (v >= Vn) continue;
      float b0 = outb[v], b1 = outb[v + 1];
#pragma unroll
      for (int i = 0; i < 2; ++i) {
        int mrow = m0g + wm * 32 + i * 16 + r0;
#pragma unroll
        for (int h = 0; h < 2; ++h) {
          int m = mrow + h * 8;
          int bb = m & 255;
          float* dst = out + ((size_t)bb * Sn + t) * Vn + v;
          float2 o;
          o.x = accH[i][nt][h * 2 + 0] + b0;
          o.y = accH[i][nt][h * 2 + 1] + b1;
          *(float2*)dst = o;
        }
      }
    }
  }
}

extern "C" void kernel_launch(void* const* d_in, const int* in_sizes, int n_in,
                              void* d_out, int out_size) {
  const float* enc  = (const float*)d_in[0];
  const int*   tgt  = (const int*)  d_in[1];
  const float* emb  = (const float*)d_in[2];
  const float* Wih  = (const float*)d_in[3];
  const float* Whh  = (const float*)d_in[4];
  const float* bih  = (const float*)d_in[5];
  const float* bhh  = (const float*)d_in[6];
  // d_in[7..9] = attn_W, attn_b, v_w : dead (softmax over single source pos)
  const float* outW = (const float*)d_in[10];
  const float* outb = (const float*)d_in[11];
  float* out = (float*)d_out;

  cudaFuncSetAttribute(fused_kernel, cudaFuncAttributeMaxDynamicSharedMemorySize, FUSED_SMEM);

  prep_all<<<2177, 256>>>(enc, emb, Wih, Whh, bih, bhh, outW);
  fused_kernel<<<NCTA, 256, FUSED_SMEM>>>(tgt, outb, out);
}

// round 10
// speedup vs baseline: 1.0757x; 1.0757x over previous
#include <cuda_runtime.h>
#include <cuda_bf16.h>
#include <cuda_fp16.h>
#include <math.h>
#include <stdint.h>

#define Bn 256
#define Sn 141
#define Vn 1000
#define En 256
#define Hn 512
#define G4 2048   // 4*H
#define VP 1024   // padded vocab

#define NC_STEP 128         // recurrence CTAs (4 groups of 32)
#define NCTA    148         // persistent CTAs (1/SM)
#define NOUT    (Sn * 32)   // out tiles: per t, 2 m-tiles x 16 n-tiles

// ---------------- device scratch ----------------
__device__ float d_embgateP[(size_t)Vn * G4];     // [v][jp] fp32
__device__ float d_encgateP[(size_t)Bn * G4];     // [b][jp] fp32
__device__ __half d_Whh_h[(size_t)G4 * Hn];       // [jp][k] fp16 hi
__device__ __half d_Whh_l[(size_t)G4 * Hn];       // [jp][k] fp16 lo * 2^12
__device__ __half d_outW_h[(size_t)VP * Hn];      // [v][k] fp16 (single chain)
__device__ __half d_hs_f16[(size_t)Sn * Bn * Hn]; // [t][b][k] fp16

// sync state (reset by prep kernel each replay); 128B-spaced counters
__device__ unsigned d_countg[4 * 32];
__device__ unsigned d_senseg[4 * 32];
__device__ unsigned d_wq;

__device__ __forceinline__ int jperm(int j) {
  return ((j & 511) >> 4) * 64 + (j >> 9) * 16 + (j & 15);
}

// ---------------- PTX helpers (plain sm_80+ only) ----------------
__device__ __forceinline__ void cp16(uint32_t dst, const void* src) {
  asm volatile("cp.async.cg.shared.global [%0], [%1], 16;" :: "r"(dst), "l"(src));
}
__device__ __forceinline__ void cp_commit() { asm volatile("cp.async.commit_group;"); }
__device__ __forceinline__ void cp_wait0() { asm volatile("cp.async.wait_group 0;" ::: "memory"); }
__device__ __forceinline__ void cp_wait1() { asm volatile("cp.async.wait_group 1;" ::: "memory"); }
__device__ __forceinline__ void cp_wait2() { asm volatile("cp.async.wait_group 2;" ::: "memory"); }

__device__ __forceinline__ void ldm4(uint32_t& r0, uint32_t& r1, uint32_t& r2, uint32_t& r3,
                                     uint32_t addr) {
  asm volatile("ldmatrix.sync.aligned.m8n8.x4.shared.b16 {%0,%1,%2,%3}, [%4];"
               : "=r"(r0), "=r"(r1), "=r"(r2), "=r"(r3) : "r"(addr));
}
__device__ __forceinline__ void mma_f16(float* d, const uint32_t* a, uint32_t b0, uint32_t b1) {
  asm volatile(
    "mma.sync.aligned.m16n8k16.row.col.f32.f16.f16.f32 "
    "{%0,%1,%2,%3}, {%4,%5,%6,%7}, {%8,%9}, {%0,%1,%2,%3};"
    : "+f"(d[0]), "+f"(d[1]), "+f"(d[2]), "+f"(d[3])
    : "r"(a[0]), "r"(a[1]), "r"(a[2]), "r"(a[3]), "r"(b0), "r"(b1));
}
__device__ __forceinline__ unsigned ld_acq(unsigned* p) {
  unsigned v;
  asm volatile("ld.acquire.gpu.u32 %0, [%1];" : "=r"(v) : "l"(p) : "memory");
  return v;
}

// ---------------- smem layout (recurrence) ----------------
#define BH_RES   0                     // 65536
#define BL_RES   65536                 // 65536
#define A_BUFS   131072                // 4 x 8192
#define ADD_EMB  163840                // [64][64] f32
#define ADD_ENC  180224
#define GS_OFF   196608                // [64][68] f32
#define GS_STRIDE 68
#define FUSED_SMEM 214016
// Out path (reuses offset 0): A fp16 128 rows + B 64 rows per buffer (24K)
#define STG_O    24576
#define OA_OFF   0
#define OB_HI    16384

// ---------------------------------------------------------------------------
// Merged prep kernel
// ---------------------------------------------------------------------------
#define MMA16(As, Bs) do {                                                       \
    _Pragma("unroll")                                                            \
    for (int kk = 0; kk < 16; ++kk) {                                            \
      float4 a = *(const float4*)&As[kk][ty * 4];                                \
      float4 b = *(const float4*)&Bs[kk][tx * 4];                                \
      acc[0][0] += a.x*b.x; acc[0][1] += a.x*b.y; acc[0][2] += a.x*b.z; acc[0][3] += a.x*b.w; \
      acc[1][0] += a.y*b.x; acc[1][1] += a.y*b.y; acc[1][2] += a.y*b.z; acc[1][3] += a.y*b.w; \
      acc[2][0] += a.z*b.x; acc[2][1] += a.z*b.y; acc[2][2] += a.z*b.z; acc[2][3] += a.z*b.w; \
      acc[3][0] += a.w*b.x; acc[3][1] += a.w*b.y; acc[3][2] += a.w*b.z; acc[3][3] += a.w*b.w; \
    } } while (0)

__global__ __launch_bounds__(256) void prep_all(
    const float* __restrict__ enc, const float* __restrict__ emb,
    const float* __restrict__ Wih, const float* __restrict__ Whh,
    const float* __restrict__ bih, const float* __restrict__ bhh,
    const float* __restrict__ outW) {
  __shared__ float As[16][64];
  __shared__ float Bs[16][64];
  int bid = blockIdx.x;
  int tid = threadIdx.x;

  if (bid < 640) {
    bool is_emb = bid < 512;
    int m0, n0;
    if (is_emb) { m0 = (bid & 15) * 64; n0 = (bid >> 4) * 64; }
    else        { int b2 = bid - 512; m0 = (b2 & 3) * 64; n0 = (b2 >> 2) * 64; }
    int tx = tid & 15, ty = tid >> 4;
    int lr = tid >> 2, lq = tid & 3;
    float acc[4][4] = {};
    for (int kc = 0; kc < En; kc += 16) {
      float4 av = make_float4(0.f, 0.f, 0.f, 0.f);
      float4 bv;
      if (is_emb) {
        if (m0 + lr < Vn)
          av = *(const float4*)(emb + (size_t)(m0 + lr) * En + kc + lq * 4);
        bv = *(const float4*)(Wih + (size_t)(n0 + lr) * (2 * En) + kc + lq * 4);
      } else {
        av = *(const float4*)(enc + (size_t)(m0 + lr) * En + kc + lq * 4);
        bv = *(const float4*)(Wih + (size_t)(n0 + lr) * (2 * En) + En + kc + lq * 4);
      }
      __syncthreads();
      As[lq*4+0][lr] = av.x; As[lq*4+1][lr] = av.y; As[lq*4+2][lr] = av.z; As[lq*4+3][lr] = av.w;
      Bs[lq*4+0][lr] = bv.x; Bs[lq*4+1][lr] = bv.y; Bs[lq*4+2][lr] = bv.z; Bs[lq*4+3][lr] = bv.w;
      __syncthreads();
      MMA16(As, Bs);
    }
#pragma unroll
    for (int ii = 0; ii < 4; ++ii) {
      int m = m0 + ty * 4 + ii;
      if (is_emb && m >= Vn) continue;
#pragma unroll
      for (int jj = 0; jj < 4; ++jj) {
        int n = n0 + tx * 4 + jj;
        if (is_emb)
          d_embgateP[(size_t)m * G4 + jperm(n)] = acc[ii][jj];
        else
          d_encgateP[(size_t)m * G4 + jperm(n)] = acc[ii][jj] + bih[n] + bhh[n];
      }
    }
  } else if (bid < 1664) {
    int i = (bid - 640) * 256 + tid;
    int e0 = i * 4;
    int j = e0 >> 9, k0 = e0 & 511;
    int jp = jperm(j);
    float4 x = *(const float4*)(Whh + e0);
    __half h[4], l[4];
    float xs[4] = {x.x, x.y, x.z, x.w};
#pragma unroll
    for (int q = 0; q < 4; ++q) {
      h[q] = __float2half_rn(xs[q]);
      l[q] = __float2half_rn((xs[q] - __half2float(h[q])) * 4096.f);
    }
    *(uint2*)(d_Whh_h + (size_t)jp * Hn + k0) = *(const uint2*)h;
    *(uint2*)(d_Whh_l + (size_t)jp * Hn + k0) = *(const uint2*)l;
  } else if (bid < 2176) {
    int i = (bid - 1664) * 256 + tid;
    int e0 = i * 4;
    int v = e0 >> 9;
    __half h[4];
    if (v < Vn) {
      float4 x = *(const float4*)(outW + e0);
      h[0] = __float2half_rn(x.x); h[1] = __float2half_rn(x.y);
      h[2] = __float2half_rn(x.z); h[3] = __float2half_rn(x.w);
    } else {
#pragma unroll
      for (int q = 0; q < 4; ++q) h[q] = __float2half_rn(0.f);
    }
    *(uint2*)(d_outW_h + e0) = *(const uint2*)h;
  } else {
    if (tid < 128) d_countg[tid] = 0;
    else if (tid < 256) d_senseg[tid - 128] = 0;
    if (tid == 0) d_wq = 0;
  }
}

// ============================================================================
// Recurrence: CTA tile 64x64, warp tile 16x32 (8 warps). B resident in smem.
// ============================================================================
#define LOADA_R(c, buf, AP)  do {                                                \
    int kc = (c) * 64;                                                           \
    uint32_t st = su + A_BUFS + (buf) * 8192;                                    \
    int row = tid >> 2;                                                          \
    int sg0 = (tid & 3) * 2;                                                     \
    uint32_t sw = (uint32_t)(row & 7) * 16;                                      \
    _Pragma("unroll")                                                            \
    for (int q = 0; q < 2; ++q) {                                                \
      int sg = sg0 + q;                                                          \
      uint32_t so = (uint32_t)row * 128 + (((uint32_t)(sg * 16)) ^ sw);          \
      cp16(st + so, (AP) + (size_t)row * Hn + kc + sg * 8);                      \
    }                                                                            \
    cp_commit();                                                                 \
  } while (0)

__device__ __forceinline__ void compute_chunk_r(
    float accH[4][4], float accL[4][4], uint32_t abase,
    uint32_t bhbase, uint32_t blbase, int wm, int wn, int lane) {
  int lr = lane & 7;
  int sel = lane >> 3;
  int a_roff = (sel & 1) * 8;
  int a_koff = (sel & 2) * 8;
  int b_koff = (sel & 1) * 16;
  int b_roff = (sel & 2) * 4;
  uint32_t swm = (uint32_t)(lr * 16);

#pragma unroll
  for (int ks = 0; ks < 4; ++ks) {
    int kb = ks * 32;
    uint32_t a[4], bh[2][4], bl[2][4];
    {
      int row = wm * 16 + lr + a_roff;
      uint32_t off = (uint32_t)row * 128 + (((uint32_t)(kb + a_koff)) ^ swm);
      ldm4(a[0], a[1], a[2], a[3], abase + off);
    }
#pragma unroll
    for (int p = 0; p < 2; ++p) {
      int row = wn * 32 + p * 16 + lr + b_roff;
      uint32_t off = (uint32_t)row * 128 + (((uint32_t)(kb + b_koff)) ^ swm);
      ldm4(bh[p][0], bh[p][1], bh[p][2], bh[p][3], bhbase + off);
      ldm4(bl[p][0], bl[p][1], bl[p][2], bl[p][3], blbase + off);
    }
#pragma unroll
    for (int nt = 0; nt < 4; ++nt) {
      int p = nt >> 1, q = (nt & 1) * 2;
      mma_f16(accH[nt], a, bh[p][q], bh[p][q + 1]);
      mma_f16(accL[nt], a, bl[p][q], bl[p][q + 1]);
    }
  }
}

// ============================================================================
// Out tile: CTA tile 128x64, warp tile 32x32, single fp16 chain, 2-deep bufs.
// ============================================================================
#define LOADC_O(c, buf, AP, BhP)  do {                                           \
    int kc = (c) * 64;                                                           \
    uint32_t st = su + (buf) * STG_O;                                            \
    {                                                                            \
      int rowA = tid >> 1;                                                       \
      int sg0 = (tid & 1) * 4;                                                   \
      uint32_t swA = (uint32_t)(rowA & 7) * 16;                                  \
      _Pragma("unroll")                                                          \
      for (int q = 0; q < 4; ++q) {                                              \
        int sg = sg0 + q;                                                        \
        uint32_t so = (uint32_t)rowA * 128 + (((uint32_t)(sg * 16)) ^ swA);      \
        cp16(st + OA_OFF + so, (AP) + (size_t)rowA * Hn + kc + sg * 8);          \
      }                                                                          \
    }                                                                            \
    {                                                                            \
      int rB = tid >> 2;                                                         \
      int sg0 = (tid & 3) * 2;                                                   \
      uint32_t swB = (uint32_t)(rB & 7) * 16;                                    \
      _Pragma("unroll")                                                          \
      for (int q = 0; q < 2; ++q) {                                              \
        int sg = sg0 + q;                                                        \
        uint32_t so = (uint32_t)rB * 128 + (((uint32_t)(sg * 16)) ^ swB);        \
        cp16(st + OB_HI + so, (BhP) + (size_t)rB * Hn + kc + sg * 8);            \
      }                                                                          \
    }                                                                            \
    cp_commit();                                                                 \
  } while (0)

__device__ __forceinline__ void compute_chunk_o(
    float accH[2][4][4], uint32_t su, int buf, int wm, int wn, int lane) {
  uint32_t base = su + buf * STG_O;
  int lr = lane & 7;
  int sel = lane >> 3;
  int a_roff = (sel & 1) * 8;
  int a_koff = (sel & 2) * 8;
  int b_koff = (sel & 1) * 16;
  int b_roff = (sel & 2) * 4;
  uint32_t swm = (uint32_t)(lr * 16);

#pragma unroll
  for (int ks = 0; ks < 4; ++ks) {
    int kb = ks * 32;
    uint32_t a[2][4], bh[2][4];
#pragma unroll
    for (int i = 0; i < 2; ++i) {
      int row = wm * 32 + i * 16 + lr + a_roff;
      uint32_t off = (uint32_t)row * 128 + (((uint32_t)(kb + a_koff)) ^ swm);
      ldm4(a[i][0], a[i][1], a[i][2], a[i][3], base + OA_OFF + off);
    }
#pragma unroll
    for (int p = 0; p < 2; ++p) {
      int row = wn * 32 + p * 16 + lr + b_roff;
      uint32_t off = (uint32_t)row * 128 + (((uint32_t)(kb + b_koff)) ^ swm);
      ldm4(bh[p][0], bh[p][1], bh[p][2], bh[p][3], base + OB_HI + off);
    }
#pragma unroll
    for (int i = 0; i < 2; ++i) {
#pragma unroll
      for (int nt = 0; nt < 4; ++nt) {
        int p = nt >> 1, q = (nt & 1) * 2;
        mma_f16(accH[i][nt], a[i], bh[p][q], bh[p][q + 1]);
      }
    }
  }
}

// ---------------------------------------------------------------------------
// Persistent fused kernel.
// ---------------------------------------------------------------------------
__global__ __launch_bounds__(256, 1) void fused_kernel(
    const int* __restrict__ tgt, const float* __restrict__ outb,
    float* __restrict__ out) {
  extern __shared__ __align__(1024) char smem[];
  __shared__ unsigned sidx;
  uint32_t su = (uint32_t)__cvta_generic_to_shared(smem);
  int tid = threadIdx.x;
  int lane = tid & 31, wid = tid >> 5;
  int wm = wid >> 1, wn = wid & 1;

  if (blockIdx.x < NC_STEP) {
    // ========== recurrence: CTA tile 64 b-rows x 64 jp-cols ==========
    int mi = blockIdx.x >> 5, nblk = blockIdx.x & 31;
    int m0 = mi * 64, n0 = nblk * 64;
    unsigned* myCount = &d_countg[mi * 32];
    unsigned* mySense = &d_senseg[mi * 32];

    // ---- resident loads: B (Whh tile) + enc addend ----
    {
      const __half* Bh = d_Whh_h + (size_t)n0 * Hn;
      const __half* Bl = d_Whh_l + (size_t)n0 * Hn;
      int row = tid >> 2;
      int sg0 = (tid & 3) * 2;
      uint32_t sw = (uint32_t)(row & 7) * 16;
#pragma unroll
      for (int c = 0; c < 8; ++c) {
#pragma unroll
        for (int q = 0; q < 2; ++q) {
          int sg = sg0 + q;
          uint32_t so = (uint32_t)row * 128 + (((uint32_t)(sg * 16)) ^ sw);
          cp16(su + BH_RES + c * 8192 + so, Bh + (size_t)row * Hn + c * 64 + sg * 8);
          cp16(su + BL_RES + c * 8192 + so, Bl + (size_t)row * Hn + c * 64 + sg * 8);
        }
      }
      int r = tid >> 2, sg0e = (tid & 3) * 4;
      const float* sc = d_encgateP + (size_t)(m0 + r) * G4 + n0;
      uint32_t dc = su + ADD_ENC + r * 256;
#pragma unroll
      for (int q = 0; q < 4; ++q)
        cp16(dc + (sg0e + q) * 16, sc + (sg0e + q) * 4);
      cp_commit();
      cp_wait0();
    }
    __syncthreads();

    int em_r = tid >> 2, em_sg = (tid & 3) * 4;
    int ep_m = tid >> 2, ep_k0 = (tid & 3) * 4;
    int ep_b = m0 + ep_m;
    int ep_kbase = nblk * 16 + ep_k0;
    const float* aE = (const float*)(smem + ADD_EMB) + ep_m * 64;
    const float* aC = (const float*)(smem + ADD_ENC) + ep_m * 64;
    float cpv[4] = {0.f, 0.f, 0.f, 0.f};

    for (int t = 0; t < Sn; ++t) {
      // emb addend for this step
      {
        int tok = tgt[(size_t)(m0 + em_r) * Sn + t];
        const float* se = d_embgateP + (size_t)tok * G4 + n0;
        uint32_t de = su + ADD_EMB + em_r * 256;
#pragma unroll
        for (int q = 0; q < 4; ++q)
          cp16(de + (em_sg + q) * 16, se + (em_sg + q) * 4);
        cp_commit();
      }

      if (t > 0) {
        float accH[4][4] = {};
        float accL[4][4] = {};
        const __half* A = d_hs_f16 + ((size_t)(t - 1) * Bn + m0) * Hn;
        LOADA_R(0, 0, A);
        LOADA_R(1, 1, A);
        LOADA_R(2, 2, A);
#pragma unroll 1
        for (int c = 0; c < 8; ++c) {
          if (c <= 5) cp_wait2();
          else if (c == 6) cp_wait1();
          else cp_wait0();
          __syncthreads();
          compute_chunk_r(accH, accL,
                          su + A_BUFS + (c & 3) * 8192,
                          su + BH_RES + c * 8192,
                          su + BL_RES + c * 8192, wm, wn, lane);
          if (c + 3 < 8) LOADA_R(c + 3, (c + 3) & 3, A);
        }
        __syncthreads();
        float* Gs = (float*)(smem + GS_OFF);
        int r0 = (lane >> 2), c0 = (lane & 3) * 2;
        const float kinv = 1.f / 4096.f;
#pragma unroll
        for (int nt = 0; nt < 4; ++nt) {
          int row = wm * 16 + r0;
          int col = wn * 32 + nt * 8 + c0;
          Gs[row * GS_STRIDE + col]           = accH[nt][0] + accL[nt][0] * kinv;
          Gs[row * GS_STRIDE + col + 1]       = accH[nt][1] + accL[nt][1] * kinv;
          Gs[(row + 8) * GS_STRIDE + col]     = accH[nt][2] + accL[nt][2] * kinv;
          Gs[(row + 8) * GS_STRIDE + col + 1] = accH[nt][3] + accL[nt][3] * kinv;
        }
      } else {
        cp_wait0();
      }
      __syncthreads();

      // ---- fused LSTM elementwise: 4 cells/thread ----
      const float* Gs = (const float*)(smem + GS_OFF);
      __half hf[4];
#pragma unroll
      for (int q = 0; q < 4; ++q) {
        int kk = ep_k0 + q;
        float gi = aE[kk]      + aC[kk];
        float gf = aE[16 + kk] + aC[16 + kk];
        float gg = aE[32 + kk] + aC[32 + kk];
        float go = aE[48 + kk] + aC[48 + kk];
        if (t > 0) {
          gi += Gs[ep_m * GS_STRIDE + kk];
          gf += Gs[ep_m * GS_STRIDE + 16 + kk];
          gg += Gs[ep_m * GS_STRIDE + 32 + kk];
          go += Gs[ep_m * GS_STRIDE + 48 + kk];
        }
        float iv = 1.f / (1.f + expf(-gi));
        float fv = 1.f / (1.f + expf(-gf));
        float gv = tanhf(gg);
        float ov = 1.f / (1.f + expf(-go));
        float cc = fv * cpv[q] + iv * gv;
        cpv[q] = cc;
        hf[q] = __float2half_rn(ov * tanhf(cc));
      }
      *(uint2*)(d_hs_f16 + ((size_t)t * Bn + ep_b) * Hn + ep_kbase) = *(const uint2*)hf;

      // ---- per-group (32-CTA) barrier: atomic arrivals, sense-word wait ----
      __threadfence();
      __syncthreads();
      if (tid == 0) {
        unsigned old = atomicAdd(myCount, 1);
        if (old == 31) {
          atomicExch(myCount, 0);
          __threadfence();
          atomicAdd(mySense, 1);
        } else {
          while (ld_acq(mySense) < (unsigned)(t + 1)) { }
        }
      }
      __syncthreads();
    }
  }

  // ========== out-GEMM worker pool (all CTAs) ==========
  for (;;) {
    __syncthreads();
    if (tid == 0) sidx = atomicAdd(&d_wq, 1);
    __syncthreads();
    unsigned idx = sidx;
    if (idx >= NOUT) break;
    int t = idx >> 5;
    int sub = idx & 31;
    int mtile = sub >> 4;
    int m0g = t * Bn + mtile * 128;
    int n0 = (sub & 15) * 64;

    if (tid == 0) {
      unsigned* sA = &d_senseg[(mtile * 2) * 32];
      unsigned* sB = &d_senseg[(mtile * 2 + 1) * 32];
      while (ld_acq(sA) < (unsigned)(t + 1) || ld_acq(sB) < (unsigned)(t + 1))
        __nanosleep(128);
    }
    __syncthreads();

    const __half* A  = d_hs_f16 + (size_t)m0g * Hn;
    const __half* Bh = d_outW_h + (size_t)n0 * Hn;

    float accH[2][4][4] = {};
    LOADC_O(0, 0, A, Bh);
    LOADC_O(1, 1, A, Bh);
#pragma unroll 1
    for (int c = 0; c < 8; ++c) {
      if (c < 7) cp_wait1(); else cp_wait0();
      __syncthreads();
      compute_chunk_o(accH, su, c & 1, wm, wn, lane);
      __syncthreads();
      if (c + 2 < 8) LOADC_O(c + 2, c & 1, A, Bh);
    }

    int r0 = lane >> 2, c0 = (lane & 3) * 2;
#pragma unroll
    for (int nt = 0; nt < 4; ++nt) {
      int v = n0 + wn * 32 + nt * 8 + c0;
      if (v >= Vn) continue;
      float b0 = outb[v], b1 = outb[v + 1];
#pragma unroll
      for (int i = 0; i < 2; ++i) {
        int mrow = m0g + wm * 32 + i * 16 + r0;
#pragma unroll
        for (int h = 0; h < 2; ++h) {
          int m = mrow + h * 8;
          int bb = m & 255;
          float* dst = out + ((size_t)bb * Sn + t) * Vn + v;
          float2 o;
          o.x = accH[i][nt][h * 2 + 0] + b0;
          o.y = accH[i][nt][h * 2 + 1] + b1;
          *(float2*)dst = o;
        }
      }
    }
  }
}

extern "C" void kernel_launch(void* const* d_in, const int* in_sizes, int n_in,
                              void* d_out, int out_size) {
  const float* enc  = (const float*)d_in[0];
  const int*   tgt  = (const int*)  d_in[1];
  const float* emb  = (const float*)d_in[2];
  const float* Wih  = (const float*)d_in[3];
  const float* Whh  = (const float*)d_in[4];
  const float* bih  = (const float*)d_in[5];
  const float* bhh  = (const float*)d_in[6];
  // d_in[7..9] = attn_W, attn_b, v_w : dead (softmax over single source pos)
  const float* outW = (const float*)d_in[10];
  const float* outb = (const float*)d_in[11];
  float* out = (float*)d_out;

  cudaFuncSetAttribute(fused_kernel, cudaFuncAttributeMaxDynamicSharedMemorySize, FUSED_SMEM);

  prep_all<<<2177, 256>>>(enc, emb, Wih, Whh, bih, bhh, outW);
  fused_kernel<<<NCTA, 256, FUSED_SMEM>>>(tgt, outb, out);
}

// round 11
// speedup vs baseline: 1.7055x; 1.5855x over previous
#include <cuda_runtime.h>
#include <cuda_bf16.h>
#include <cuda_fp16.h>
#include <math.h>
#include <stdint.h>

#define Bn 256
#define Sn 141
#define Vn 1000
#define En 256
#define Hn 512
#define G4 2048   // 4*H
#define VP 1024   // padded vocab

#define NC_STEP 128         // recurrence CTAs (4 groups of 32)
#define NCTA    148         // persistent CTAs (1/SM)
#define NOUT    (Sn * 32)   // out tiles: per t, 2 m-tiles x 16 n-tiles

// ---------------- device scratch ----------------
__device__ float d_embgateP[(size_t)Vn * G4];     // [v][jp] fp32
__device__ float d_encgateP[(size_t)Bn * G4];     // [b][jp] fp32
__device__ __half d_Whh_h[(size_t)G4 * Hn];       // [jp][k] fp16 (single chain)
__device__ __half d_outW_h[(size_t)VP * Hn];      // [v][k] fp16 hi
__device__ __half d_outW_l[(size_t)VP * Hn];      // [v][k] fp16 lo * 2^12
__device__ __half d_hs_f16[(size_t)Sn * Bn * Hn]; // [t][b][k] fp16

// sync state (reset by prep kernel each replay); 128B-spaced counters
__device__ unsigned d_countg[4 * 32];
__device__ unsigned d_senseg[4 * 32];
__device__ unsigned d_wq;

__device__ __forceinline__ int jperm(int j) {
  return ((j & 511) >> 4) * 64 + (j >> 9) * 16 + (j & 15);
}

// ---------------- PTX helpers (plain sm_80+ only) ----------------
__device__ __forceinline__ void cp16(uint32_t dst, const void* src) {
  asm volatile("cp.async.cg.shared.global [%0], [%1], 16;" :: "r"(dst), "l"(src));
}
__device__ __forceinline__ void cp_commit() { asm volatile("cp.async.commit_group;"); }
__device__ __forceinline__ void cp_wait0() { asm volatile("cp.async.wait_group 0;" ::: "memory"); }
__device__ __forceinline__ void cp_wait1() { asm volatile("cp.async.wait_group 1;" ::: "memory"); }
__device__ __forceinline__ void cp_wait2() { asm volatile("cp.async.wait_group 2;" ::: "memory"); }

__device__ __forceinline__ void ldm4(uint32_t& r0, uint32_t& r1, uint32_t& r2, uint32_t& r3,
                                     uint32_t addr) {
  asm volatile("ldmatrix.sync.aligned.m8n8.x4.shared.b16 {%0,%1,%2,%3}, [%4];"
               : "=r"(r0), "=r"(r1), "=r"(r2), "=r"(r3) : "r"(addr));
}
__device__ __forceinline__ void mma_f16(float* d, const uint32_t* a, uint32_t b0, uint32_t b1) {
  asm volatile(
    "mma.sync.aligned.m16n8k16.row.col.f32.f16.f16.f32 "
    "{%0,%1,%2,%3}, {%4,%5,%6,%7}, {%8,%9}, {%0,%1,%2,%3};"
    : "+f"(d[0]), "+f"(d[1]), "+f"(d[2]), "+f"(d[3])
    : "r"(a[0]), "r"(a[1]), "r"(a[2]), "r"(a[3]), "r"(b0), "r"(b1));
}
__device__ __forceinline__ unsigned ld_acq(unsigned* p) {
  unsigned v;
  asm volatile("ld.acquire.gpu.u32 %0, [%1];" : "=r"(v) : "l"(p) : "memory");
  return v;
}

// ---------------- smem layout (recurrence) ----------------
#define BH_RES   0                     // 8 chunks x 8192 = 65536
#define A_BUFS   65536                 // 4 x 8192 = 32768
#define ADD_EMB  98304                 // [64][64] f32 = 16384
#define ADD_ENC  114688                // 16384
#define GS_OFF   131072                // [64][68] f32 = 17408
#define GS_STRIDE 68
#define FUSED_SMEM 148480
// Out path (reuses offset 0): A fp16 128 rows + B hi/lo 64 rows (32K/buffer)
#define STG_O    32768
#define OA_OFF   0
#define OB_HI    16384
#define OB_LO    24576

// ---------------------------------------------------------------------------
// Merged prep kernel
// ---------------------------------------------------------------------------
#define MMA16(As, Bs) do {                                                       \
    _Pragma("unroll")                                                            \
    for (int kk = 0; kk < 16; ++kk) {                                            \
      float4 a = *(const float4*)&As[kk][ty * 4];                                \
      float4 b = *(const float4*)&Bs[kk][tx * 4];                                \
      acc[0][0] += a.x*b.x; acc[0][1] += a.x*b.y; acc[0][2] += a.x*b.z; acc[0][3] += a.x*b.w; \
      acc[1][0] += a.y*b.x; acc[1][1] += a.y*b.y; acc[1][2] += a.y*b.z; acc[1][3] += a.y*b.w; \
      acc[2][0] += a.z*b.x; acc[2][1] += a.z*b.y; acc[2][2] += a.z*b.z; acc[2][3] += a.z*b.w; \
      acc[3][0] += a.w*b.x; acc[3][1] += a.w*b.y; acc[3][2] += a.w*b.z; acc[3][3] += a.w*b.w; \
    } } while (0)

__global__ __launch_bounds__(256) void prep_all(
    const float* __restrict__ enc, const float* __restrict__ emb,
    const float* __restrict__ Wih, const float* __restrict__ Whh,
    const float* __restrict__ bih, const float* __restrict__ bhh,
    const float* __restrict__ outW) {
  __shared__ float As[16][64];
  __shared__ float Bs[16][64];
  int bid = blockIdx.x;
  int tid = threadIdx.x;

  if (bid < 640) {
    bool is_emb = bid < 512;
    int m0, n0;
    if (is_emb) { m0 = (bid & 15) * 64; n0 = (bid >> 4) * 64; }
    else        { int b2 = bid - 512; m0 = (b2 & 3) * 64; n0 = (b2 >> 2) * 64; }
    int tx = tid & 15, ty = tid >> 4;
    int lr = tid >> 2, lq = tid & 3;
    float acc[4][4] = {};
    for (int kc = 0; kc < En; kc += 16) {
      float4 av = make_float4(0.f, 0.f, 0.f, 0.f);
      float4 bv;
      if (is_emb) {
        if (m0 + lr < Vn)
          av = *(const float4*)(emb + (size_t)(m0 + lr) * En + kc + lq * 4);
        bv = *(const float4*)(Wih + (size_t)(n0 + lr) * (2 * En) + kc + lq * 4);
      } else {
        av = *(const float4*)(enc + (size_t)(m0 + lr) * En + kc + lq * 4);
        bv = *(const float4*)(Wih + (size_t)(n0 + lr) * (2 * En) + En + kc + lq * 4);
      }
      __syncthreads();
      As[lq*4+0][lr] = av.x; As[lq*4+1][lr] = av.y; As[lq*4+2][lr] = av.z; As[lq*4+3][lr] = av.w;
      Bs[lq*4+0][lr] = bv.x; Bs[lq*4+1][lr] = bv.y; Bs[lq*4+2][lr] = bv.z; Bs[lq*4+3][lr] = bv.w;
      __syncthreads();
      MMA16(As, Bs);
    }
#pragma unroll
    for (int ii = 0; ii < 4; ++ii) {
      int m = m0 + ty * 4 + ii;
      if (is_emb && m >= Vn) continue;
#pragma unroll
      for (int jj = 0; jj < 4; ++jj) {
        int n = n0 + tx * 4 + jj;
        if (is_emb)
          d_embgateP[(size_t)m * G4 + jperm(n)] = acc[ii][jj];
        else
          d_encgateP[(size_t)m * G4 + jperm(n)] = acc[ii][jj] + bih[n] + bhh[n];
      }
    }
  } else if (bid < 1664) {
    // ---- Whh fp32 -> fp16 (single chain), row-permute [jp][k] ----
    int i = (bid - 640) * 256 + tid;
    int e0 = i * 4;
    int j = e0 >> 9, k0 = e0 & 511;
    int jp = jperm(j);
    float4 x = *(const float4*)(Whh + e0);
    __half h[4];
    h[0] = __float2half_rn(x.x); h[1] = __float2half_rn(x.y);
    h[2] = __float2half_rn(x.z); h[3] = __float2half_rn(x.w);
    *(uint2*)(d_Whh_h + (size_t)jp * Hn + k0) = *(const uint2*)h;
  } else if (bid < 2176) {
    // ---- outW fp32 -> fp16 hi/lo (2 chains), zero-padded ----
    int i = (bid - 1664) * 256 + tid;
    int e0 = i * 4;
    int v = e0 >> 9;
    __half h[4], l[4];
    if (v < Vn) {
      float4 x = *(const float4*)(outW + e0);
      float xs[4] = {x.x, x.y, x.z, x.w};
#pragma unroll
      for (int q = 0; q < 4; ++q) {
        h[q] = __float2half_rn(xs[q]);
        l[q] = __float2half_rn((xs[q] - __half2float(h[q])) * 4096.f);
      }
    } else {
#pragma unroll
      for (int q = 0; q < 4; ++q) { h[q] = __float2half_rn(0.f); l[q] = h[q]; }
    }
    *(uint2*)(d_outW_h + e0) = *(const uint2*)h;
    *(uint2*)(d_outW_l + e0) = *(const uint2*)l;
  } else {
    if (tid < 128) d_countg[tid] = 0;
    else if (tid < 256) d_senseg[tid - 128] = 0;
    if (tid == 0) d_wq = 0;
  }
}

// ============================================================================
// Recurrence: CTA tile 64x64, warp tile 16x32 (8 warps). B resident in smem,
// single fp16 chain.
// ============================================================================
#define LOADA_R(c, buf, AP)  do {                                                \
    int kc = (c) * 64;                                                           \
    uint32_t st = su + A_BUFS + (buf) * 8192;                                    \
    int row = tid >> 2;                                                          \
    int sg0 = (tid & 3) * 2;                                                     \
    uint32_t sw = (uint32_t)(row & 7) * 16;                                      \
    _Pragma("unroll")                                                            \
    for (int q = 0; q < 2; ++q) {                                                \
      int sg = sg0 + q;                                                          \
      uint32_t so = (uint32_t)row * 128 + (((uint32_t)(sg * 16)) ^ sw);          \
      cp16(st + so, (AP) + (size_t)row * Hn + kc + sg * 8);                      \
    }                                                                            \
    cp_commit();                                                                 \
  } while (0)

__device__ __forceinline__ void compute_chunk_r(
    float accH[4][4], uint32_t abase, uint32_t bhbase, int wm, int wn, int lane) {
  int lr = lane & 7;
  int sel = lane >> 3;
  int a_roff = (sel & 1) * 8;
  int a_koff = (sel & 2) * 8;
  int b_koff = (sel & 1) * 16;
  int b_roff = (sel & 2) * 4;
  uint32_t swm = (uint32_t)(lr * 16);

#pragma unroll
  for (int ks = 0; ks < 4; ++ks) {
    int kb = ks * 32;
    uint32_t a[4], bh[2][4];
    {
      int row = wm * 16 + lr + a_roff;
      uint32_t off = (uint32_t)row * 128 + (((uint32_t)(kb + a_koff)) ^ swm);
      ldm4(a[0], a[1], a[2], a[3], abase + off);
    }
#pragma unroll
    for (int p = 0; p < 2; ++p) {
      int row = wn * 32 + p * 16 + lr + b_roff;
      uint32_t off = (uint32_t)row * 128 + (((uint32_t)(kb + b_koff)) ^ swm);
      ldm4(bh[p][0], bh[p][1], bh[p][2], bh[p][3], bhbase + off);
    }
#pragma unroll
    for (int nt = 0; nt < 4; ++nt) {
      int p = nt >> 1, q = (nt & 1) * 2;
      mma_f16(accH[nt], a, bh[p][q], bh[p][q + 1]);
    }
  }
}

// ============================================================================
// Out tile: CTA tile 128x64, warp tile 32x32, fp16 hi/lo 2-chain (as in the
// 1456us config), 2-deep buffers.
// ============================================================================
#define LOADC_O(c, buf, AP, BhP, BlP)  do {                                      \
    int kc = (c) * 64;                                                           \
    uint32_t st = su + (buf) * STG_O;                                            \
    {                                                                            \
      int rowA = tid >> 1;                                                       \
      int sg0 = (tid & 1) * 4;                                                   \
      uint32_t swA = (uint32_t)(rowA & 7) * 16;                                  \
      _Pragma("unroll")                                                          \
      for (int q = 0; q < 4; ++q) {                                              \
        int sg = sg0 + q;                                                        \
        uint32_t so = (uint32_t)rowA * 128 + (((uint32_t)(sg * 16)) ^ swA);      \
        cp16(st + OA_OFF + so, (AP) + (size_t)rowA * Hn + kc + sg * 8);          \
      }                                                                          \
    }                                                                            \
    {                                                                            \
      int rB = tid >> 2;                                                         \
      int sg0 = (tid & 3) * 2;                                                   \
      uint32_t swB = (uint32_t)(rB & 7) * 16;                                    \
      _Pragma("unroll")                                                          \
      for (int q = 0; q < 2; ++q) {                                              \
        int sg = sg0 + q;                                                        \
        uint32_t so = (uint32_t)rB * 128 + (((uint32_t)(sg * 16)) ^ swB);        \
        cp16(st + OB_HI + so, (BhP) + (size_t)rB * Hn + kc + sg * 8);            \
        cp16(st + OB_LO + so, (BlP) + (size_t)rB * Hn + kc + sg * 8);            \
      }                                                                          \
    }                                                                            \
    cp_commit();                                                                 \
  } while (0)

__device__ __forceinline__ void compute_chunk_o(
    float accH[2][4][4], float accL[2][4][4], uint32_t su, int buf,
    int wm, int wn, int lane) {
  uint32_t base = su + buf * STG_O;
  int lr = lane & 7;
  int sel = lane >> 3;
  int a_roff = (sel & 1) * 8;
  int a_koff = (sel & 2) * 8;
  int b_koff = (sel & 1) * 16;
  int b_roff = (sel & 2) * 4;
  uint32_t swm = (uint32_t)(lr * 16);

#pragma unroll
  for (int ks = 0; ks < 4; ++ks) {
    int kb = ks * 32;
    uint32_t a[2][4], bh[2][4], bl[2][4];
#pragma unroll
    for (int i = 0; i < 2; ++i) {
      int row = wm * 32 + i * 16 + lr + a_roff;
      uint32_t off = (uint32_t)row * 128 + (((uint32_t)(kb + a_koff)) ^ swm);
      ldm4(a[i][0], a[i][1], a[i][2], a[i][3], base + OA_OFF + off);
    }
#pragma unroll
    for (int p = 0; p < 2; ++p) {
      int row = wn * 32 + p * 16 + lr + b_roff;
      uint32_t off = (uint32_t)row * 128 + (((uint32_t)(kb + b_koff)) ^ swm);
      ldm4(bh[p][0], bh[p][1], bh[p][2], bh[p][3], base + OB_HI + off);
      ldm4(bl[p][0], bl[p][1], bl[p][2], bl[p][3], base + OB_LO + off);
    }
#pragma unroll
    for (int i = 0; i < 2; ++i) {
#pragma unroll
      for (int nt = 0; nt < 4; ++nt) {
        int p = nt >> 1, q = (nt & 1) * 2;
        mma_f16(accH[i][nt], a[i], bh[p][q], bh[p][q + 1]);
        mma_f16(accL[i][nt], a[i], bl[p][q], bl[p][q + 1]);
      }
    }
  }
}

// ---------------------------------------------------------------------------
// Persistent fused kernel.
// ---------------------------------------------------------------------------
__global__ __launch_bounds__(256, 1) void fused_kernel(
    const int* __restrict__ tgt, const float* __restrict__ outb,
    float* __restrict__ out) {
  extern __shared__ __align__(1024) char smem[];
  __shared__ unsigned sidx;
  uint32_t su = (uint32_t)__cvta_generic_to_shared(smem);
  int tid = threadIdx.x;
  int lane = tid & 31, wid = tid >> 5;
  int wm = wid >> 1, wn = wid & 1;

  if (blockIdx.x < NC_STEP) {
    // ========== recurrence: CTA tile 64 b-rows x 64 jp-cols ==========
    int mi = blockIdx.x >> 5, nblk = blockIdx.x & 31;
    int m0 = mi * 64, n0 = nblk * 64;
    unsigned* myCount = &d_countg[mi * 32];
    unsigned* mySense = &d_senseg[mi * 32];

    // ---- resident loads: B (Whh tile, single chain) + enc addend ----
    {
      const __half* Bh = d_Whh_h + (size_t)n0 * Hn;
      int row = tid >> 2;
      int sg0 = (tid & 3) * 2;
      uint32_t sw = (uint32_t)(row & 7) * 16;
#pragma unroll
      for (int c = 0; c < 8; ++c) {
#pragma unroll
        for (int q = 0; q < 2; ++q) {
          int sg = sg0 + q;
          uint32_t so = (uint32_t)row * 128 + (((uint32_t)(sg * 16)) ^ sw);
          cp16(su + BH_RES + c * 8192 + so, Bh + (size_t)row * Hn + c * 64 + sg * 8);
        }
      }
      int r = tid >> 2, sg0e = (tid & 3) * 4;
      const float* sc = d_encgateP + (size_t)(m0 + r) * G4 + n0;
      uint32_t dc = su + ADD_ENC + r * 256;
#pragma unroll
      for (int q = 0; q < 4; ++q)
        cp16(dc + (sg0e + q) * 16, sc + (sg0e + q) * 4);
      cp_commit();
      cp_wait0();
    }
    __syncthreads();

    int em_r = tid >> 2, em_sg = (tid & 3) * 4;
    int ep_m = tid >> 2, ep_k0 = (tid & 3) * 4;
    int ep_b = m0 + ep_m;
    int ep_kbase = nblk * 16 + ep_k0;
    const float* aE = (const float*)(smem + ADD_EMB) + ep_m * 64;
    const float* aC = (const float*)(smem + ADD_ENC) + ep_m * 64;
    float cpv[4] = {0.f, 0.f, 0.f, 0.f};

    for (int t = 0; t < Sn; ++t) {
      // emb addend for this step
      {
        int tok = tgt[(size_t)(m0 + em_r) * Sn + t];
        const float* se = d_embgateP + (size_t)tok * G4 + n0;
        uint32_t de = su + ADD_EMB + em_r * 256;
#pragma unroll
        for (int q = 0; q < 4; ++q)
          cp16(de + (em_sg + q) * 16, se + (em_sg + q) * 4);
        cp_commit();
      }

      if (t > 0) {
        float accH[4][4] = {};
        const __half* A = d_hs_f16 + ((size_t)(t - 1) * Bn + m0) * Hn;
        LOADA_R(0, 0, A);
        LOADA_R(1, 1, A);
        LOADA_R(2, 2, A);
#pragma unroll 1
        for (int c = 0; c < 8; ++c) {
          if (c <= 5) cp_wait2();
          else if (c == 6) cp_wait1();
          else cp_wait0();
          __syncthreads();
          compute_chunk_r(accH,
                          su + A_BUFS + (c & 3) * 8192,
                          su + BH_RES + c * 8192, wm, wn, lane);
          if (c + 3 < 8) LOADA_R(c + 3, (c + 3) & 3, A);
        }
        __syncthreads();
        float* Gs = (float*)(smem + GS_OFF);
        int r0 = (lane >> 2), c0 = (lane & 3) * 2;
#pragma unroll
        for (int nt = 0; nt < 4; ++nt) {
          int row = wm * 16 + r0;
          int col = wn * 32 + nt * 8 + c0;
          Gs[row * GS_STRIDE + col]           = accH[nt][0];
          Gs[row * GS_STRIDE + col + 1]       = accH[nt][1];
          Gs[(row + 8) * GS_STRIDE + col]     = accH[nt][2];
          Gs[(row + 8) * GS_STRIDE + col + 1] = accH[nt][3];
        }
      } else {
        cp_wait0();
      }
      __syncthreads();

      // ---- fused LSTM elementwise: 4 cells/thread ----
      const float* Gs = (const float*)(smem + GS_OFF);
      __half hf[4];
#pragma unroll
      for (int q = 0; q < 4; ++q) {
        int kk = ep_k0 + q;
        float gi = aE[kk]      + aC[kk];
        float gf = aE[16 + kk] + aC[16 + kk];
        float gg = aE[32 + kk] + aC[32 + kk];
        float go = aE[48 + kk] + aC[48 + kk];
        if (t > 0) {
          gi += Gs[ep_m * GS_STRIDE + kk];
          gf += Gs[ep_m * GS_STRIDE + 16 + kk];
          gg += Gs[ep_m * GS_STRIDE + 32 + kk];
          go += Gs[ep_m * GS_STRIDE + 48 + kk];
        }
        float iv = 1.f / (1.f + expf(-gi));
        float fv = 1.f / (1.f + expf(-gf));
        float gv = tanhf(gg);
        float ov = 1.f / (1.f + expf(-go));
        float cc = fv * cpv[q] + iv * gv;
        cpv[q] = cc;
        hf[q] = __float2half_rn(ov * tanhf(cc));
      }
      *(uint2*)(d_hs_f16 + ((size_t)t * Bn + ep_b) * Hn + ep_kbase) = *(const uint2*)hf;

      // ---- per-group (32-CTA) barrier: atomic arrivals, sense-word wait ----
      __threadfence();
      __syncthreads();
      if (tid == 0) {
        unsigned old = atomicAdd(myCount, 1);
        if (old == 31) {
          atomicExch(myCount, 0);
          __threadfence();
          atomicAdd(mySense, 1);
        } else {
          while (ld_acq(mySense) < (unsigned)(t + 1)) { }
        }
      }
      __syncthreads();
    }
  }

  // ========== out-GEMM worker pool (all CTAs) ==========
  for (;;) {
    __syncthreads();
    if (tid == 0) sidx = atomicAdd(&d_wq, 1);
    __syncthreads();
    unsigned idx = sidx;
    if (idx >= NOUT) break;
    int t = idx >> 5;
    int sub = idx & 31;
    int mtile = sub >> 4;
    int m0g = t * Bn + mtile * 128;
    int n0 = (sub & 15) * 64;

    if (tid == 0) {
      unsigned* sA = &d_senseg[(mtile * 2) * 32];
      unsigned* sB = &d_senseg[(mtile * 2 + 1) * 32];
      while (ld_acq(sA) < (unsigned)(t + 1) || ld_acq(sB) < (unsigned)(t + 1))
        __nanosleep(128);
    }
    __syncthreads();

    const __half* A  = d_hs_f16 + (size_t)m0g * Hn;
    const __half* Bh = d_outW_h + (size_t)n0 * Hn;
    const __half* Bl = d_outW_l + (size_t)n0 * Hn;

    float accH[2][4][4] = {};
    float accL[2][4][4] = {};
    LOADC_O(0, 0, A, Bh, Bl);
    LOADC_O(1, 1, A, Bh, Bl);
#pragma unroll 1
    for (int c = 0; c < 8; ++c) {
      if (c < 7) cp_wait1(); else cp_wait0();
      __syncthreads();
      compute_chunk_o(accH, accL, su, c & 1, wm, wn, lane);
      __syncthreads();
      if (c + 2 < 8) LOADC_O(c + 2, c & 1, A, Bh, Bl);
    }

    int r0 = lane >> 2, c0 = (lane & 3) * 2;
#pragma unroll
    for (int nt = 0; nt < 4; ++nt) {
      int v = n0 + wn * 32 + nt * 8 + c0;
      if (v >= Vn) continue;
      float b0 = outb[v], b1 = outb[v + 1];
#pragma unroll
      for (int i = 0; i < 2; ++i) {
        int mrow = m0g + wm * 32 + i * 16 + r0;
#pragma unroll
        for (int h = 0; h < 2; ++h) {
          int m = mrow + h * 8;
          int bb = m & 255;
          float* dst = out + ((size_t)bb * Sn + t) * Vn + v;
          float2 o;
          o.x = accH[i][nt][h * 2 + 0] + accL[i][nt][h * 2 + 0] * (1.f / 4096.f) + b0;
          o.y = accH[i][nt][h * 2 + 1] + accL[i][nt][h * 2 + 1] * (1.f / 4096.f) + b1;
          *(float2*)dst = o;
        }
      }
    }
  }
}

extern "C" void kernel_launch(void* const* d_in, const int* in_sizes, int n_in,
                              void* d_out, int out_size) {
  const float* enc  = (const float*)d_in[0];
  const int*   tgt  = (const int*)  d_in[1];
  const float* emb  = (const float*)d_in[2];
  const float* Wih  = (const float*)d_in[3];
  const float* Whh  = (const float*)d_in[4];
  const float* bih  = (const float*)d_in[5];
  const float* bhh  = (const float*)d_in[6];
  // d_in[7..9] = attn_W, attn_b, v_w : dead (softmax over single source pos)
  const float* outW = (const float*)d_in[10];
  const float* outb = (const float*)d_in[11];
  float* out = (float*)d_out;

  cudaFuncSetAttribute(fused_kernel, cudaFuncAttributeMaxDynamicSharedMemorySize, FUSED_SMEM);

  prep_all<<<2177, 256>>>(enc, emb, Wih, Whh, bih, bhh, outW);
  fused_kernel<<<NCTA, 256, FUSED_SMEM>>>(tgt, outb, out);
}

// round 12
// speedup vs baseline: 1.8603x; 1.0907x over previous
#include <cuda_runtime.h>
#include <cuda_bf16.h>
#include <cuda_fp16.h>
#include <math.h>
#include <stdint.h>

#define Bn 256
#define Sn 141
#define Vn 1000
#define En 256
#define Hn 512
#define G4 2048   // 4*H
#define VP 1024   // padded vocab

#define NC_STEP 128         // recurrence CTAs (4 groups of 32)
#define NCTA    148         // persistent CTAs (1/SM)
#define NOUT    (Sn * 32)   // out tiles: per t, 2 m-tiles x 16 n-tiles

// ---------------- device scratch ----------------
__device__ float d_embgateP[(size_t)Vn * G4];     // [v][jp] fp32
__device__ float d_encgateP[(size_t)Bn * G4];     // [b][jp] fp32
__device__ __half d_Whh_h[(size_t)G4 * Hn];       // [jp][k] fp16 (single chain)
__device__ __half d_outW_h[(size_t)VP * Hn];      // [v][k] fp16 (single chain)
__device__ __half d_hs_f16[(size_t)Sn * Bn * Hn]; // [t][b][k] fp16

// sync state (reset by prep kernel each replay); 128B-spaced counters
__device__ unsigned d_countg[4 * 32];
__device__ unsigned d_senseg[4 * 32];
__device__ unsigned d_wq;

__device__ __forceinline__ int jperm(int j) {
  return ((j & 511) >> 4) * 64 + (j >> 9) * 16 + (j & 15);
}

// ---------------- PTX helpers (plain sm_80+ only) ----------------
__device__ __forceinline__ void cp16(uint32_t dst, const void* src) {
  asm volatile("cp.async.cg.shared.global [%0], [%1], 16;" :: "r"(dst), "l"(src));
}
__device__ __forceinline__ void cp_commit() { asm volatile("cp.async.commit_group;"); }
__device__ __forceinline__ void cp_wait0() { asm volatile("cp.async.wait_group 0;" ::: "memory"); }
__device__ __forceinline__ void cp_wait1() { asm volatile("cp.async.wait_group 1;" ::: "memory"); }
__device__ __forceinline__ void cp_wait2() { asm volatile("cp.async.wait_group 2;" ::: "memory"); }

__device__ __forceinline__ void ldm4(uint32_t& r0, uint32_t& r1, uint32_t& r2, uint32_t& r3,
                                     uint32_t addr) {
  asm volatile("ldmatrix.sync.aligned.m8n8.x4.shared.b16 {%0,%1,%2,%3}, [%4];"
               : "=r"(r0), "=r"(r1), "=r"(r2), "=r"(r3) : "r"(addr));
}
__device__ __forceinline__ void mma_f16(float* d, const uint32_t* a, uint32_t b0, uint32_t b1) {
  asm volatile(
    "mma.sync.aligned.m16n8k16.row.col.f32.f16.f16.f32 "
    "{%0,%1,%2,%3}, {%4,%5,%6,%7}, {%8,%9}, {%0,%1,%2,%3};"
    : "+f"(d[0]), "+f"(d[1]), "+f"(d[2]), "+f"(d[3])
    : "r"(a[0]), "r"(a[1]), "r"(a[2]), "r"(a[3]), "r"(b0), "r"(b1));
}
__device__ __forceinline__ unsigned ld_acq(unsigned* p) {
  unsigned v;
  asm volatile("ld.acquire.gpu.u32 %0, [%1];" : "=r"(v) : "l"(p) : "memory");
  return v;
}

// ---------------- smem layout (recurrence) ----------------
#define BH_RES   0                     // 8 chunks x 8192 = 65536
#define A_BUFS   65536                 // 4 x 8192 = 32768
#define ADD_EMB  98304                 // [64][64] f32 = 16384
#define ADD_ENC  114688                // 16384
#define GS_OFF   131072                // [64][68] f32 = 17408
#define GS_STRIDE 68
#define FUSED_SMEM 148480
// Out path (reuses offset 0): A fp16 128 rows + B 64 rows (24K/buffer)
#define STG_O    24576
#define OA_OFF   0
#define OB_HI    16384

// ---------------------------------------------------------------------------
// Merged prep kernel
// ---------------------------------------------------------------------------
#define MMA16(As, Bs) do {                                                       \
    _Pragma("unroll")                                                            \
    for (int kk = 0; kk < 16; ++kk) {                                            \
      float4 a = *(const float4*)&As[kk][ty * 4];                                \
      float4 b = *(const float4*)&Bs[kk][tx * 4];                                \
      acc[0][0] += a.x*b.x; acc[0][1] += a.x*b.y; acc[0][2] += a.x*b.z; acc[0][3] += a.x*b.w; \
      acc[1][0] += a.y*b.x; acc[1][1] += a.y*b.y; acc[1][2] += a.y*b.z; acc[1][3] += a.y*b.w; \
      acc[2][0] += a.z*b.x; acc[2][1] += a.z*b.y; acc[2][2] += a.z*b.z; acc[2][3] += a.z*b.w; \
      acc[3][0] += a.w*b.x; acc[3][1] += a.w*b.y; acc[3][2] += a.w*b.z; acc[3][3] += a.w*b.w; \
    } } while (0)

__global__ __launch_bounds__(256) void prep_all(
    const float* __restrict__ enc, const float* __restrict__ emb,
    const float* __restrict__ Wih, const float* __restrict__ Whh,
    const float* __restrict__ bih, const float* __restrict__ bhh,
    const float* __restrict__ outW) {
  __shared__ float As[16][64];
  __shared__ float Bs[16][64];
  int bid = blockIdx.x;
  int tid = threadIdx.x;

  if (bid < 640) {
    bool is_emb = bid < 512;
    int m0, n0;
    if (is_emb) { m0 = (bid & 15) * 64; n0 = (bid >> 4) * 64; }
    else        { int b2 = bid - 512; m0 = (b2 & 3) * 64; n0 = (b2 >> 2) * 64; }
    int tx = tid & 15, ty = tid >> 4;
    int lr = tid >> 2, lq = tid & 3;
    float acc[4][4] = {};
    for (int kc = 0; kc < En; kc += 16) {
      float4 av = make_float4(0.f, 0.f, 0.f, 0.f);
      float4 bv;
      if (is_emb) {
        if (m0 + lr < Vn)
          av = *(const float4*)(emb + (size_t)(m0 + lr) * En + kc + lq * 4);
        bv = *(const float4*)(Wih + (size_t)(n0 + lr) * (2 * En) + kc + lq * 4);
      } else {
        av = *(const float4*)(enc + (size_t)(m0 + lr) * En + kc + lq * 4);
        bv = *(const float4*)(Wih + (size_t)(n0 + lr) * (2 * En) + En + kc + lq * 4);
      }
      __syncthreads();
      As[lq*4+0][lr] = av.x; As[lq*4+1][lr] = av.y; As[lq*4+2][lr] = av.z; As[lq*4+3][lr] = av.w;
      Bs[lq*4+0][lr] = bv.x; Bs[lq*4+1][lr] = bv.y; Bs[lq*4+2][lr] = bv.z; Bs[lq*4+3][lr] = bv.w;
      __syncthreads();
      MMA16(As, Bs);
    }
#pragma unroll
    for (int ii = 0; ii < 4; ++ii) {
      int m = m0 + ty * 4 + ii;
      if (is_emb && m >= Vn) continue;
#pragma unroll
      for (int jj = 0; jj < 4; ++jj) {
        int n = n0 + tx * 4 + jj;
        if (is_emb)
          d_embgateP[(size_t)m * G4 + jperm(n)] = acc[ii][jj];
        else
          d_encgateP[(size_t)m * G4 + jperm(n)] = acc[ii][jj] + bih[n] + bhh[n];
      }
    }
  } else if (bid < 1664) {
    // ---- Whh fp32 -> fp16 (single chain), row-permute [jp][k] ----
    int i = (bid - 640) * 256 + tid;
    int e0 = i * 4;
    int j = e0 >> 9, k0 = e0 & 511;
    int jp = jperm(j);
    float4 x = *(const float4*)(Whh + e0);
    __half h[4];
    h[0] = __float2half_rn(x.x); h[1] = __float2half_rn(x.y);
    h[2] = __float2half_rn(x.z); h[3] = __float2half_rn(x.w);
    *(uint2*)(d_Whh_h + (size_t)jp * Hn + k0) = *(const uint2*)h;
  } else if (bid < 2176) {
    // ---- outW fp32 -> fp16 (single chain), zero-padded ----
    int i = (bid - 1664) * 256 + tid;
    int e0 = i * 4;
    int v = e0 >> 9;
    __half h[4];
    if (v < Vn) {
      float4 x = *(const float4*)(outW + e0);
      h[0] = __float2half_rn(x.x); h[1] = __float2half_rn(x.y);
      h[2] = __float2half_rn(x.z); h[3] = __float2half_rn(x.w);
    } else {
#pragma unroll
      for (int q = 0; q < 4; ++q) h[q] = __float2half_rn(0.f);
    }
    *(uint2*)(d_outW_h + e0) = *(const uint2*)h;
  } else {
    if (tid < 128) d_countg[tid] = 0;
    else if (tid < 256) d_senseg[tid - 128] = 0;
    if (tid == 0) d_wq = 0;
  }
}

// ============================================================================
// Recurrence: CTA tile 64x64, warp tile 16x32 (8 warps). B resident in smem,
// single fp16 chain.
// ============================================================================
#define LOADA_R(c, buf, AP)  do {                                                \
    int kc = (c) * 64;                                                           \
    uint32_t st = su + A_BUFS + (buf) * 8192;                                    \
    int row = tid >> 2;                                                          \
    int sg0 = (tid & 3) * 2;                                                     \
    uint32_t sw = (uint32_t)(row & 7) * 16;                                      \
    _Pragma("unroll")                                                            \
    for (int q = 0; q < 2; ++q) {                                                \
      int sg = sg0 + q;                                                          \
      uint32_t so = (uint32_t)row * 128 + (((uint32_t)(sg * 16)) ^ sw);          \
      cp16(st + so, (AP) + (size_t)row * Hn + kc + sg * 8);                      \
    }                                                                            \
    cp_commit();                                                                 \
  } while (0)

__device__ __forceinline__ void compute_chunk_r(
    float accH[4][4], uint32_t abase, uint32_t bhbase, int wm, int wn, int lane) {
  int lr = lane & 7;
  int sel = lane >> 3;
  int a_roff = (sel & 1) * 8;
  int a_koff = (sel & 2) * 8;
  int b_koff = (sel & 1) * 16;
  int b_roff = (sel & 2) * 4;
  uint32_t swm = (uint32_t)(lr * 16);

#pragma unroll
  for (int ks = 0; ks < 4; ++ks) {
    int kb = ks * 32;
    uint32_t a[4], bh[2][4];
    {
      int row = wm * 16 + lr + a_roff;
      uint32_t off = (uint32_t)row * 128 + (((uint32_t)(kb + a_koff)) ^ swm);
      ldm4(a[0], a[1], a[2], a[3], abase + off);
    }
#pragma unroll
    for (int p = 0; p < 2; ++p) {
      int row = wn * 32 + p * 16 + lr + b_roff;
      uint32_t off = (uint32_t)row * 128 + (((uint32_t)(kb + b_koff)) ^ swm);
      ldm4(bh[p][0], bh[p][1], bh[p][2], bh[p][3], bhbase + off);
    }
#pragma unroll
    for (int nt = 0; nt < 4; ++nt) {
      int p = nt >> 1, q = (nt & 1) * 2;
      mma_f16(accH[nt], a, bh[p][q], bh[p][q + 1]);
    }
  }
}

// ============================================================================
// Out tile: CTA tile 128x64, warp tile 32x32, single fp16 chain, 2-deep bufs.
// ============================================================================
#define LOADC_O(c, buf, AP, BhP)  do {                                           \
    int kc = (c) * 64;                                                           \
    uint32_t st = su + (buf) * STG_O;                                            \
    {                                                                            \
      int rowA = tid >> 1;                                                       \
      int sg0 = (tid & 1) * 4;                                                   \
      uint32_t swA = (uint32_t)(rowA & 7) * 16;                                  \
      _Pragma("unroll")                                                          \
      for (int q = 0; q < 4; ++q) {                                              \
        int sg = sg0 + q;                                                        \
        uint32_t so = (uint32_t)rowA * 128 + (((uint32_t)(sg * 16)) ^ swA);      \
        cp16(st + OA_OFF + so, (AP) + (size_t)rowA * Hn + kc + sg * 8);          \
      }                                                                          \
    }                                                                            \
    {                                                                            \
      int rB = tid >> 2;                                                         \
      int sg0 = (tid & 3) * 2;                                                   \
      uint32_t swB = (uint32_t)(rB & 7) * 16;                                    \
      _Pragma("unroll")                                                          \
      for (int q = 0; q < 2; ++q) {                                              \
        int sg = sg0 + q;                                                        \
        uint32_t so = (uint32_t)rB * 128 + (((uint32_t)(sg * 16)) ^ swB);        \
        cp16(st + OB_HI + so, (BhP) + (size_t)rB * Hn + kc + sg * 8);            \
      }                                                                          \
    }                                                                            \
    cp_commit();                                                                 \
  } while (0)

__device__ __forceinline__ void compute_chunk_o(
    float accH[2][4][4], uint32_t su, int buf, int wm, int wn, int lane) {
  uint32_t base = su + buf * STG_O;
  int lr = lane & 7;
  int sel = lane >> 3;
  int a_roff = (sel & 1) * 8;
  int a_koff = (sel & 2) * 8;
  int b_koff = (sel & 1) * 16;
  int b_roff = (sel & 2) * 4;
  uint32_t swm = (uint32_t)(lr * 16);

#pragma unroll
  for (int ks = 0; ks < 4; ++ks) {
    int kb = ks * 32;
    uint32_t a[2][4], bh[2][4];
#pragma unroll
    for (int i = 0; i < 2; ++i) {
      int row = wm * 32 + i * 16 + lr + a_roff;
      uint32_t off = (uint32_t)row * 128 + (((uint32_t)(kb + a_koff)) ^ swm);
      ldm4(a[i][0], a[i][1], a[i][2], a[i][3], base + OA_OFF + off);
    }
#pragma unroll
    for (int p = 0; p < 2; ++p) {
      int row = wn * 32 + p * 16 + lr + b_roff;
      uint32_t off = (uint32_t)row * 128 + (((uint32_t)(kb + b_koff)) ^ swm);
      ldm4(bh[p][0], bh[p][1], bh[p][2], bh[p][3], base + OB_HI + off);
    }
#pragma unroll
    for (int i = 0; i < 2; ++i) {
#pragma unroll
      for (int nt = 0; nt < 4; ++nt) {
        int p = nt >> 1, q = (nt & 1) * 2;
        mma_f16(accH[i][nt], a[i], bh[p][q], bh[p][q + 1]);
      }
    }
  }
}

// ---------------------------------------------------------------------------
// Persistent fused kernel.
// ---------------------------------------------------------------------------
__global__ __launch_bounds__(256, 1) void fused_kernel(
    const int* __restrict__ tgt, const float* __restrict__ outb,
    float* __restrict__ out) {
  extern __shared__ __align__(1024) char smem[];
  __shared__ unsigned sidx;
  uint32_t su = (uint32_t)__cvta_generic_to_shared(smem);
  int tid = threadIdx.x;
  int lane = tid & 31, wid = tid >> 5;
  int wm = wid >> 1, wn = wid & 1;

  if (blockIdx.x < NC_STEP) {
    // ========== recurrence: CTA tile 64 b-rows x 64 jp-cols ==========
    int mi = blockIdx.x >> 5, nblk = blockIdx.x & 31;
    int m0 = mi * 64, n0 = nblk * 64;
    unsigned* myCount = &d_countg[mi * 32];
    unsigned* mySense = &d_senseg[mi * 32];

    // ---- resident loads: B (Whh tile, single chain) + enc addend ----
    {
      const __half* Bh = d_Whh_h + (size_t)n0 * Hn;
      int row = tid >> 2;
      int sg0 = (tid & 3) * 2;
      uint32_t sw = (uint32_t)(row & 7) * 16;
#pragma unroll
      for (int c = 0; c < 8; ++c) {
#pragma unroll
        for (int q = 0; q < 2; ++q) {
          int sg = sg0 + q;
          uint32_t so = (uint32_t)row * 128 + (((uint32_t)(sg * 16)) ^ sw);
          cp16(su + BH_RES + c * 8192 + so, Bh + (size_t)row * Hn + c * 64 + sg * 8);
        }
      }
      int r = tid >> 2, sg0e = (tid & 3) * 4;
      const float* sc = d_encgateP + (size_t)(m0 + r) * G4 + n0;
      uint32_t dc = su + ADD_ENC + r * 256;
#pragma unroll
      for (int q = 0; q < 4; ++q)
        cp16(dc + (sg0e + q) * 16, sc + (sg0e + q) * 4);
      cp_commit();
      cp_wait0();
    }
    __syncthreads();

    int em_r = tid >> 2, em_sg = (tid & 3) * 4;
    int ep_m = tid >> 2, ep_k0 = (tid & 3) * 4;
    int ep_b = m0 + ep_m;
    int ep_kbase = nblk * 16 + ep_k0;
    const float* aE = (const float*)(smem + ADD_EMB) + ep_m * 64;
    const float* aC = (const float*)(smem + ADD_ENC) + ep_m * 64;
    float cpv[4] = {0.f, 0.f, 0.f, 0.f};

    for (int t = 0; t < Sn; ++t) {
      // emb addend for this step
      {
        int tok = tgt[(size_t)(m0 + em_r) * Sn + t];
        const float* se = d_embgateP + (size_t)tok * G4 + n0;
        uint32_t de = su + ADD_EMB + em_r * 256;
#pragma unroll
        for (int q = 0; q < 4; ++q)
          cp16(de + (em_sg + q) * 16, se + (em_sg + q) * 4);
        cp_commit();
      }

      if (t > 0) {
        float accH[4][4] = {};
        const __half* A = d_hs_f16 + ((size_t)(t - 1) * Bn + m0) * Hn;
        LOADA_R(0, 0, A);
        LOADA_R(1, 1, A);
        LOADA_R(2, 2, A);
#pragma unroll 1
        for (int c = 0; c < 8; ++c) {
          if (c <= 5) cp_wait2();
          else if (c == 6) cp_wait1();
          else cp_wait0();
          __syncthreads();
          compute_chunk_r(accH,
                          su + A_BUFS + (c & 3) * 8192,
                          su + BH_RES + c * 8192, wm, wn, lane);
          if (c + 3 < 8) LOADA_R(c + 3, (c + 3) & 3, A);
        }
        // stage accums to Gs (disjoint region; no sync needed before writes)
        float* Gs = (float*)(smem + GS_OFF);
        int r0 = (lane >> 2), c0 = (lane & 3) * 2;
#pragma unroll
        for (int nt = 0; nt < 4; ++nt) {
          int row = wm * 16 + r0;
          int col = wn * 32 + nt * 8 + c0;
          Gs[row * GS_STRIDE + col]           = accH[nt][0];
          Gs[row * GS_STRIDE + col + 1]       = accH[nt][1];
          Gs[(row + 8) * GS_STRIDE + col]     = accH[nt][2];
          Gs[(row + 8) * GS_STRIDE + col + 1] = accH[nt][3];
        }
      } else {
        cp_wait0();
      }
      __syncthreads();

      // ---- fused LSTM elementwise: 4 cells/thread ----
      const float* Gs = (const float*)(smem + GS_OFF);
      __half hf[4];
#pragma unroll
      for (int q = 0; q < 4; ++q) {
        int kk = ep_k0 + q;
        float gi = aE[kk]      + aC[kk];
        float gf = aE[16 + kk] + aC[16 + kk];
        float gg = aE[32 + kk] + aC[32 + kk];
        float go = aE[48 + kk] + aC[48 + kk];
        if (t > 0) {
          gi += Gs[ep_m * GS_STRIDE + kk];
          gf += Gs[ep_m * GS_STRIDE + 16 + kk];
          gg += Gs[ep_m * GS_STRIDE + 32 + kk];
          go += Gs[ep_m * GS_STRIDE + 48 + kk];
        }
        float iv = 1.f / (1.f + expf(-gi));
        float fv = 1.f / (1.f + expf(-gf));
        float gv = tanhf(gg);
        float ov = 1.f / (1.f + expf(-go));
        float cc = fv * cpv[q] + iv * gv;
        cpv[q] = cc;
        hf[q] = __float2half_rn(ov * tanhf(cc));
      }
      *(uint2*)(d_hs_f16 + ((size_t)t * Bn + ep_b) * Hn + ep_kbase) = *(const uint2*)hf;

      // ---- per-group (32-CTA) barrier: atomic arrivals, sense-word wait ----
      __threadfence();
      __syncthreads();
      if (tid == 0) {
        unsigned old = atomicAdd(myCount, 1);
        if (old == 31) {
          atomicExch(myCount, 0);
          __threadfence();
          atomicAdd(mySense, 1);
        } else {
          while (ld_acq(mySense) < (unsigned)(t + 1)) { }
        }
      }
      __syncthreads();
    }
  }

  // ========== out-GEMM worker pool (all CTAs) ==========
  for (;;) {
    __syncthreads();
    if (tid == 0) sidx = atomicAdd(&d_wq, 1);
    __syncthreads();
    unsigned idx = sidx;
    if (idx >= NOUT) break;
    int t = idx >> 5;
    int sub = idx & 31;
    int mtile = sub >> 4;
    int m0g = t * Bn + mtile * 128;
    int n0 = (sub & 15) * 64;

    if (tid == 0) {
      unsigned* sA = &d_senseg[(mtile * 2) * 32];
      unsigned* sB = &d_senseg[(mtile * 2 + 1) * 32];
      while (ld_acq(sA) < (unsigned)(t + 1) || ld_acq(sB) < (unsigned)(t + 1))
        __nanosleep(128);
    }
    __syncthreads();

    const __half* A  = d_hs_f16 + (size_t)m0g * Hn;
    const __half* Bh = d_outW_h + (size_t)n0 * Hn;

    float accH[2][4][4] = {};
    LOADC_O(0, 0, A, Bh);
    LOADC_O(1, 1, A, Bh);
#pragma unroll 1
    for (int c = 0; c < 8; ++c) {
      if (c < 7) cp_wait1(); else cp_wait0();
      __syncthreads();
      compute_chunk_o(accH, su, c & 1, wm, wn, lane);
      __syncthreads();
      if (c + 2 < 8) LOADC_O(c + 2, c & 1, A, Bh);
    }

    int r0 = lane >> 2, c0 = (lane & 3) * 2;
#pragma unroll
    for (int nt = 0; nt < 4; ++nt) {
      int v = n0 + wn * 32 + nt * 8 + c0;
      if (v >= Vn) continue;
      float b0 = outb[v], b1 = outb[v + 1];
#pragma unroll
      for (int i = 0; i < 2; ++i) {
        int mrow = m0g + wm * 32 + i * 16 + r0;
#pragma unroll
        for (int h = 0; h < 2; ++h) {
          int m = mrow + h * 8;
          int bb = m & 255;
          float* dst = out + ((size_t)bb * Sn + t) * Vn + v;
          float2 o;
          o.x = accH[i][nt][h * 2 + 0] + b0;
          o.y = accH[i][nt][h * 2 + 1] + b1;
          *(float2*)dst = o;
        }
      }
    }
  }
}

extern "C" void kernel_launch(void* const* d_in, const int* in_sizes, int n_in,
                              void* d_out, int out_size) {
  const float* enc  = (const float*)d_in[0];
  const int*   tgt  = (const int*)  d_in[1];
  const float* emb  = (const float*)d_in[2];
  const float* Wih  = (const float*)d_in[3];
  const float* Whh  = (const float*)d_in[4];
  const float* bih  = (const float*)d_in[5];
  const float* bhh  = (const float*)d_in[6];
  // d_in[7..9] = attn_W, attn_b, v_w : dead (softmax over single source pos)
  const float* outW = (const float*)d_in[10];
  const float* outb = (const float*)d_in[11];
  float* out = (float*)d_out;

  cudaFuncSetAttribute(fused_kernel, cudaFuncAttributeMaxDynamicSharedMemorySize, FUSED_SMEM);

  prep_all<<<2177, 256>>>(enc, emb, Wih, Whh, bih, bhh, outW);
  fused_kernel<<<NCTA, 256, FUSED_SMEM>>>(tgt, outb, out);
}

// round 13
// speedup vs baseline: 2.0209x; 1.0864x over previous
#include <cuda_runtime.h>
#include <cuda_bf16.h>
#include <cuda_fp16.h>
#include <math.h>
#include <stdint.h>

#define Bn 256
#define Sn 141
#define Vn 1000
#define En 256
#define Hn 512
#define G4 2048   // 4*H
#define VP 1024   // padded vocab

#define NC_STEP 128         // recurrence CTAs (4 groups of 32)
#define NCTA    148         // persistent CTAs (1/SM)
#define NOUT    (Sn * 32)   // out tiles: per t, 2 m-tiles x 16 n-tiles
#define NTHR    512         // 16 warps

// ---------------- device scratch ----------------
__device__ float d_embgateP[(size_t)Vn * G4];     // [v][jp] fp32
__device__ float d_encgateP[(size_t)Bn * G4];     // [b][jp] fp32
__device__ __half d_Whh_h[(size_t)G4 * Hn];       // [jp][k] fp16 (single chain)
__device__ __half d_outW_h[(size_t)VP * Hn];      // [v][k] fp16 (single chain)
__device__ __half d_hs_f16[(size_t)Sn * Bn * Hn]; // [t][b][k] fp16

// sync state (reset by prep kernel each replay); 128B-spaced counters
__device__ unsigned d_countg[4 * 32];
__device__ unsigned d_senseg[4 * 32];
__device__ unsigned d_wq;

__device__ __forceinline__ int jperm(int j) {
  return ((j & 511) >> 4) * 64 + (j >> 9) * 16 + (j & 15);
}

// ---------------- PTX helpers (plain sm_80+ only) ----------------
__device__ __forceinline__ void cp16(uint32_t dst, const void* src) {
  asm volatile("cp.async.cg.shared.global [%0], [%1], 16;" :: "r"(dst), "l"(src));
}
__device__ __forceinline__ void cp_commit() { asm volatile("cp.async.commit_group;"); }
__device__ __forceinline__ void cp_wait0() { asm volatile("cp.async.wait_group 0;" ::: "memory"); }
__device__ __forceinline__ void cp_wait1() { asm volatile("cp.async.wait_group 1;" ::: "memory"); }
__device__ __forceinline__ void cp_wait2() { asm volatile("cp.async.wait_group 2;" ::: "memory"); }

__device__ __forceinline__ void ldm4(uint32_t& r0, uint32_t& r1, uint32_t& r2, uint32_t& r3,
                                     uint32_t addr) {
  asm volatile("ldmatrix.sync.aligned.m8n8.x4.shared.b16 {%0,%1,%2,%3}, [%4];"
               : "=r"(r0), "=r"(r1), "=r"(r2), "=r"(r3) : "r"(addr));
}
__device__ __forceinline__ void mma_f16(float* d, const uint32_t* a, uint32_t b0, uint32_t b1) {
  asm volatile(
    "mma.sync.aligned.m16n8k16.row.col.f32.f16.f16.f32 "
    "{%0,%1,%2,%3}, {%4,%5,%6,%7}, {%8,%9}, {%0,%1,%2,%3};"
    : "+f"(d[0]), "+f"(d[1]), "+f"(d[2]), "+f"(d[3])
    : "r"(a[0]), "r"(a[1]), "r"(a[2]), "r"(a[3]), "r"(b0), "r"(b1));
}
__device__ __forceinline__ unsigned ld_acq(unsigned* p) {
  unsigned v;
  asm volatile("ld.acquire.gpu.u32 %0, [%1];" : "=r"(v) : "l"(p) : "memory");
  return v;
}

// ---------------- smem layout (recurrence) ----------------
#define BH_RES   0                     // 8 chunks x 8192 = 65536
#define A_BUFS   65536                 // 4 x 8192 = 32768
#define ADD_EMB  98304                 // [64][64] f32 = 16384
#define ADD_ENC  114688                // 16384
#define GS_OFF   131072                // [64][68] f32 = 17408
#define GS_STRIDE 68
#define FUSED_SMEM 148480
// Out path (reuses offset 0): A fp16 128 rows + B 64 rows (24K/buffer)
#define STG_O    24576
#define OA_OFF   0
#define OB_HI    16384

// ---------------------------------------------------------------------------
// Merged prep kernel (unchanged from the 1186us config, 256 threads)
// ---------------------------------------------------------------------------
#define MMA16(As, Bs) do {                                                       \
    _Pragma("unroll")                                                            \
    for (int kk = 0; kk < 16; ++kk) {                                            \
      float4 a = *(const float4*)&As[kk][ty * 4];                                \
      float4 b = *(const float4*)&Bs[kk][tx * 4];                                \
      acc[0][0] += a.x*b.x; acc[0][1] += a.x*b.y; acc[0][2] += a.x*b.z; acc[0][3] += a.x*b.w; \
      acc[1][0] += a.y*b.x; acc[1][1] += a.y*b.y; acc[1][2] += a.y*b.z; acc[1][3] += a.y*b.w; \
      acc[2][0] += a.z*b.x; acc[2][1] += a.z*b.y; acc[2][2] += a.z*b.z; acc[2][3] += a.z*b.w; \
      acc[3][0] += a.w*b.x; acc[3][1] += a.w*b.y; acc[3][2] += a.w*b.z; acc[3][3] += a.w*b.w; \
    } } while (0)

__global__ __launch_bounds__(256) void prep_all(
    const float* __restrict__ enc, const float* __restrict__ emb,
    const float* __restrict__ Wih, const float* __restrict__ Whh,
    const float* __restrict__ bih, const float* __restrict__ bhh,
    const float* __restrict__ outW) {
  __shared__ float As[16][64];
  __shared__ float Bs[16][64];
  int bid = blockIdx.x;
  int tid = threadIdx.x;

  if (bid < 640) {
    bool is_emb = bid < 512;
    int m0, n0;
    if (is_emb) { m0 = (bid & 15) * 64; n0 = (bid >> 4) * 64; }
    else        { int b2 = bid - 512; m0 = (b2 & 3) * 64; n0 = (b2 >> 2) * 64; }
    int tx = tid & 15, ty = tid >> 4;
    int lr = tid >> 2, lq = tid & 3;
    float acc[4][4] = {};
    for (int kc = 0; kc < En; kc += 16) {
      float4 av = make_float4(0.f, 0.f, 0.f, 0.f);
      float4 bv;
      if (is_emb) {
        if (m0 + lr < Vn)
          av = *(const float4*)(emb + (size_t)(m0 + lr) * En + kc + lq * 4);
        bv = *(const float4*)(Wih + (size_t)(n0 + lr) * (2 * En) + kc + lq * 4);
      } else {
        av = *(const float4*)(enc + (size_t)(m0 + lr) * En + kc + lq * 4);
        bv = *(const float4*)(Wih + (size_t)(n0 + lr) * (2 * En) + En + kc + lq * 4);
      }
      __syncthreads();
      As[lq*4+0][lr] = av.x; As[lq*4+1][lr] = av.y; As[lq*4+2][lr] = av.z; As[lq*4+3][lr] = av.w;
      Bs[lq*4+0][lr] = bv.x; Bs[lq*4+1][lr] = bv.y; Bs[lq*4+2][lr] = bv.z; Bs[lq*4+3][lr] = bv.w;
      __syncthreads();
      MMA16(As, Bs);
    }
#pragma unroll
    for (int ii = 0; ii < 4; ++ii) {
      int m = m0 + ty * 4 + ii;
      if (is_emb && m >= Vn) continue;
#pragma unroll
      for (int jj = 0; jj < 4; ++jj) {
        int n = n0 + tx * 4 + jj;
        if (is_emb)
          d_embgateP[(size_t)m * G4 + jperm(n)] = acc[ii][jj];
        else
          d_encgateP[(size_t)m * G4 + jperm(n)] = acc[ii][jj] + bih[n] + bhh[n];
      }
    }
  } else if (bid < 1664) {
    int i = (bid - 640) * 256 + tid;
    int e0 = i * 4;
    int j = e0 >> 9, k0 = e0 & 511;
    int jp = jperm(j);
    float4 x = *(const float4*)(Whh + e0);
    __half h[4];
    h[0] = __float2half_rn(x.x); h[1] = __float2half_rn(x.y);
    h[2] = __float2half_rn(x.z); h[3] = __float2half_rn(x.w);
    *(uint2*)(d_Whh_h + (size_t)jp * Hn + k0) = *(const uint2*)h;
  } else if (bid < 2176) {
    int i = (bid - 1664) * 256 + tid;
    int e0 = i * 4;
    int v = e0 >> 9;
    __half h[4];
    if (v < Vn) {
      float4 x = *(const float4*)(outW + e0);
      h[0] = __float2half_rn(x.x); h[1] = __float2half_rn(x.y);
      h[2] = __float2half_rn(x.z); h[3] = __float2half_rn(x.w);
    } else {
#pragma unroll
      for (int q = 0; q < 4; ++q) h[q] = __float2half_rn(0.f);
    }
    *(uint2*)(d_outW_h + e0) = *(const uint2*)h;
  } else {
    if (tid < 128) d_countg[tid] = 0;
    else if (tid < 256) d_senseg[tid - 128] = 0;
    if (tid == 0) d_wq = 0;
  }
}

// ============================================================================
// Recurrence: CTA tile 64x64, 16 warps, warp tile 16x16.
// ============================================================================
#define LOADA_R(c, buf, AP)  do {                                                \
    int kc = (c) * 64;                                                           \
    uint32_t st = su + A_BUFS + (buf) * 8192;                                    \
    int row = tid >> 3;                                                          \
    int sg = tid & 7;                                                            \
    uint32_t sw = (uint32_t)(row & 7) * 16;                                      \
    uint32_t so = (uint32_t)row * 128 + (((uint32_t)(sg * 16)) ^ sw);            \
    cp16(st + so, (AP) + (size_t)row * Hn + kc + sg * 8);                        \
    cp_commit();                                                                 \
  } while (0)

__device__ __forceinline__ void compute_chunk_r(
    float acc[2][4], uint32_t abase, uint32_t bhbase, int wm, int wn, int lane) {
  int lr = lane & 7;
  int sel = lane >> 3;
  int a_roff = (sel & 1) * 8;
  int a_koff = (sel & 2) * 8;          // bytes
  int b_koff = (sel & 1) * 16;         // bytes
  int b_roff = (sel & 2) * 4;
  uint32_t swm = (uint32_t)(lr * 16);

#pragma unroll
  for (int ks = 0; ks < 4; ++ks) {
    int kb = ks * 32;                  // bytes (16 k per ks)
    uint32_t a[4], bh[4];
    {
      int row = wm * 16 + lr + a_roff;
      uint32_t off = (uint32_t)row * 128 + (((uint32_t)(kb + a_koff)) ^ swm);
      ldm4(a[0], a[1], a[2], a[3], abase + off);
    }
    {
      int row = wn * 16 + lr + b_roff;
      uint32_t off = (uint32_t)row * 128 + (((uint32_t)(kb + b_koff)) ^ swm);
      ldm4(bh[0], bh[1], bh[2], bh[3], bhbase + off);
    }
    mma_f16(acc[0], a, bh[0], bh[1]);
    mma_f16(acc[1], a, bh[2], bh[3]);
  }
}

// ============================================================================
// Out tile: CTA tile 128x64, 16 warps, warp tile 32x16.
// ============================================================================
#define LOADC_O(c, buf, AP, BhP)  do {                                           \
    int kc = (c) * 64;                                                           \
    uint32_t st = su + (buf) * STG_O;                                            \
    {                                                                            \
      int rowA = tid >> 2;                                                       \
      int sg0 = (tid & 3) * 2;                                                   \
      uint32_t swA = (uint32_t)(rowA & 7) * 16;                                  \
      _Pragma("unroll")                                                          \
      for (int q = 0; q < 2; ++q) {                                              \
        int sg = sg0 + q;                                                        \
        uint32_t so = (uint32_t)rowA * 128 + (((uint32_t)(sg * 16)) ^ swA);      \
        cp16(st + OA_OFF + so, (AP) + (size_t)rowA * Hn + kc + sg * 8);          \
      }                                                                          \
    }                                                                            \
    {                                                                            \
      int rB = tid >> 3;                                                         \
      int sg = tid & 7;                                                          \
      uint32_t swB = (uint32_t)(rB & 7) * 16;                                    \
      uint32_t so = (uint32_t)rB * 128 + (((uint32_t)(sg * 16)) ^ swB);          \
      cp16(st + OB_HI + so, (BhP) + (size_t)rB * Hn + kc + sg * 8);              \
    }                                                                            \
    cp_commit();                                                                 \
  } while (0)

__device__ __forceinline__ void compute_chunk_o(
    float accH[2][2][4], uint32_t su, int buf, int wm, int wn, int lane) {
  uint32_t base = su + buf * STG_O;
  int lr = lane & 7;
  int sel = lane >> 3;
  int a_roff = (sel & 1) * 8;
  int a_koff = (sel & 2) * 8;
  int b_koff = (sel & 1) * 16;
  int b_roff = (sel & 2) * 4;
  uint32_t swm = (uint32_t)(lr * 16);

#pragma unroll
  for (int ks = 0; ks < 4; ++ks) {
    int kb = ks * 32;
    uint32_t a[2][4], bh[4];
#pragma unroll
    for (int i = 0; i < 2; ++i) {
      int row = wm * 32 + i * 16 + lr + a_roff;
      uint32_t off = (uint32_t)row * 128 + (((uint32_t)(kb + a_koff)) ^ swm);
      ldm4(a[i][0], a[i][1], a[i][2], a[i][3], base + OA_OFF + off);
    }
    {
      int row = wn * 16 + lr + b_roff;
      uint32_t off = (uint32_t)row * 128 + (((uint32_t)(kb + b_koff)) ^ swm);
      ldm4(bh[0], bh[1], bh[2], bh[3], base + OB_HI + off);
    }
#pragma unroll
    for (int i = 0; i < 2; ++i) {
      mma_f16(accH[i][0], a[i], bh[0], bh[1]);
      mma_f16(accH[i][1], a[i], bh[2], bh[3]);
    }
  }
}

// ---------------------------------------------------------------------------
// Persistent fused kernel (512 threads, 16 warps).
// ---------------------------------------------------------------------------
__global__ __launch_bounds__(NTHR, 1) void fused_kernel(
    const int* __restrict__ tgt, const float* __restrict__ outb,
    float* __restrict__ out) {
  extern __shared__ __align__(1024) char smem[];
  __shared__ unsigned sidx;
  uint32_t su = (uint32_t)__cvta_generic_to_shared(smem);
  int tid = threadIdx.x;
  int lane = tid & 31, wid = tid >> 5;
  int wm = wid >> 2, wn = wid & 3;     // 4x4 warp grid

  if (blockIdx.x < NC_STEP) {
    // ========== recurrence: CTA tile 64 b-rows x 64 jp-cols ==========
    int mi = blockIdx.x >> 5, nblk = blockIdx.x & 31;
    int m0 = mi * 64, n0 = nblk * 64;
    unsigned* myCount = &d_countg[mi * 32];
    unsigned* mySense = &d_senseg[mi * 32];

    // ---- resident loads: B (Whh tile, single chain) + enc addend ----
    {
      const __half* Bh = d_Whh_h + (size_t)n0 * Hn;
      int row = tid >> 3;
      int sg = tid & 7;
      uint32_t sw = (uint32_t)(row & 7) * 16;
      uint32_t so = (uint32_t)row * 128 + (((uint32_t)(sg * 16)) ^ sw);
#pragma unroll
      for (int c = 0; c < 8; ++c)
        cp16(su + BH_RES + c * 8192 + so, Bh + (size_t)row * Hn + c * 64 + sg * 8);
      int r = tid >> 3, sg0e = (tid & 7) * 2;
      const float* sc = d_encgateP + (size_t)(m0 + r) * G4 + n0;
      uint32_t dc = su + ADD_ENC + r * 256;
#pragma unroll
      for (int q = 0; q < 2; ++q)
        cp16(dc + (sg0e + q) * 16, sc + (sg0e + q) * 4);
      cp_commit();
      cp_wait0();
    }
    __syncthreads();

    int em_r = tid >> 3, em_sg = (tid & 7) * 2;
    int ep_m = tid >> 3, ep_k0 = (tid & 7) * 2;   // 2 cells per thread
    int ep_b = m0 + ep_m;
    int ep_kbase = nblk * 16 + ep_k0;
    const float* aE = (const float*)(smem + ADD_EMB) + ep_m * 64;
    const float* aC = (const float*)(smem + ADD_ENC) + ep_m * 64;
    float cpv[2] = {0.f, 0.f};

    for (int t = 0; t < Sn; ++t) {
      // emb addend for this step
      {
        int tok = tgt[(size_t)(m0 + em_r) * Sn + t];
        const float* se = d_embgateP + (size_t)tok * G4 + n0;
        uint32_t de = su + ADD_EMB + em_r * 256;
#pragma unroll
        for (int q = 0; q < 2; ++q)
          cp16(de + (em_sg + q) * 16, se + (em_sg + q) * 4);
        cp_commit();
      }

      if (t > 0) {
        float acc[2][4] = {};
        const __half* A = d_hs_f16 + ((size_t)(t - 1) * Bn + m0) * Hn;
        LOADA_R(0, 0, A);
        LOADA_R(1, 1, A);
        LOADA_R(2, 2, A);
#pragma unroll 1
        for (int c = 0; c < 8; ++c) {
          if (c <= 5) cp_wait2();
          else if (c == 6) cp_wait1();
          else cp_wait0();
          __syncthreads();
          compute_chunk_r(acc,
                          su + A_BUFS + (c & 3) * 8192,
                          su + BH_RES + c * 8192, wm, wn, lane);
          if (c + 3 < 8) LOADA_R(c + 3, (c + 3) & 3, A);
        }
        // stage accums to Gs (disjoint region; no sync needed before writes)
        float* Gs = (float*)(smem + GS_OFF);
        int r0 = (lane >> 2), c0 = (lane & 3) * 2;
#pragma unroll
        for (int nt = 0; nt < 2; ++nt) {
          int row = wm * 16 + r0;
          int col = wn * 16 + nt * 8 + c0;
          Gs[row * GS_STRIDE + col]           = acc[nt][0];
          Gs[row * GS_STRIDE + col + 1]       = acc[nt][1];
          Gs[(row + 8) * GS_STRIDE + col]     = acc[nt][2];
          Gs[(row + 8) * GS_STRIDE + col + 1] = acc[nt][3];
        }
      } else {
        cp_wait0();
      }
      __syncthreads();

      // ---- fused LSTM elementwise: 2 cells/thread ----
      const float* Gs = (const float*)(smem + GS_OFF);
      __half hf[2];
#pragma unroll
      for (int q = 0; q < 2; ++q) {
        int kk = ep_k0 + q;
        float gi = aE[kk]      + aC[kk];
        float gf = aE[16 + kk] + aC[16 + kk];
        float gg = aE[32 + kk] + aC[32 + kk];
        float go = aE[48 + kk] + aC[48 + kk];
        if (t > 0) {
          gi += Gs[ep_m * GS_STRIDE + kk];
          gf += Gs[ep_m * GS_STRIDE + 16 + kk];
          gg += Gs[ep_m * GS_STRIDE + 32 + kk];
          go += Gs[ep_m * GS_STRIDE + 48 + kk];
        }
        float iv = 1.f / (1.f + expf(-gi));
        float fv = 1.f / (1.f + expf(-gf));
        float gv = tanhf(gg);
        float ov = 1.f / (1.f + expf(-go));
        float cc = fv * cpv[q] + iv * gv;
        cpv[q] = cc;
        hf[q] = __float2half_rn(ov * tanhf(cc));
      }
      *(uint32_t*)(d_hs_f16 + ((size_t)t * Bn + ep_b) * Hn + ep_kbase) =
          *(const uint32_t*)hf;

      // ---- per-group (32-CTA) barrier: atomic arrivals, sense-word wait ----
      __threadfence();
      __syncthreads();
      if (tid == 0) {
        unsigned old = atomicAdd(myCount, 1);
        if (old == 31) {
          atomicExch(myCount, 0);
          __threadfence();
          atomicAdd(mySense, 1);
        } else {
          while (ld_acq(mySense) < (unsigned)(t + 1)) { }
        }
      }
      __syncthreads();
    }
  }

  // ========== out-GEMM worker pool (all CTAs) ==========
  for (;;) {
    __syncthreads();
    if (tid == 0) sidx = atomicAdd(&d_wq, 1);
    __syncthreads();
    unsigned idx = sidx;
    if (idx >= NOUT) break;
    int t = idx >> 5;
    int sub = idx & 31;
    int mtile = sub >> 4;
    int m0g = t * Bn + mtile * 128;
    int n0 = (sub & 15) * 64;

    if (tid == 0) {
      unsigned* sA = &d_senseg[(mtile * 2) * 32];
      unsigned* sB = &d_senseg[(mtile * 2 + 1) * 32];
      while (ld_acq(sA) < (unsigned)(t + 1) || ld_acq(sB) < (unsigned)(t + 1))
        __nanosleep(128);
    }
    __syncthreads();

    const __half* A  = d_hs_f16 + (size_t)m0g * Hn;
    const __half* Bh = d_outW_h + (size_t)n0 * Hn;

    float accH[2][2][4] = {};
    LOADC_O(0, 0, A, Bh);
    LOADC_O(1, 1, A, Bh);
#pragma unroll 1
    for (int c = 0; c < 8; ++c) {
      if (c < 7) cp_wait1(); else cp_wait0();
      __syncthreads();
      compute_chunk_o(accH, su, c & 1, wm, wn, lane);
      __syncthreads();
      if (c + 2 < 8) LOADC_O(c + 2, c & 1, A, Bh);
    }

    int r0 = lane >> 2, c0 = (lane & 3) * 2;
#pragma unroll
    for (int nt = 0; nt < 2; ++nt) {
      int v = n0 + wn * 16 + nt * 8 + c0;
      if (v >= Vn) continue;
      float b0 = outb[v], b1 = outb[v + 1];
#pragma unroll
      for (int i = 0; i < 2; ++i) {
        int mrow = m0g + wm * 32 + i * 16 + r0;
#pragma unroll
        for (int h = 0; h < 2; ++h) {
          int m = mrow + h * 8;
          int bb = m & 255;
          float* dst = out + ((size_t)bb * Sn + t) * Vn + v;
          float2 o;
          o.x = accH[i][nt][h * 2 + 0] + b0;
          o.y = accH[i][nt][h * 2 + 1] + b1;
          *(float2*)dst = o;
        }
      }
    }
  }
}

extern "C" void kernel_launch(void* const* d_in, const int* in_sizes, int n_in,
                              void* d_out, int out_size) {
  const float* enc  = (const float*)d_in[0];
  const int*   tgt  = (const int*)  d_in[1];
  const float* emb  = (const float*)d_in[2];
  const float* Wih  = (const float*)d_in[3];
  const float* Whh  = (const float*)d_in[4];
  const float* bih  = (const float*)d_in[5];
  const float* bhh  = (const float*)d_in[6];
  // d_in[7..9] = attn_W, attn_b, v_w : dead (softmax over single source pos)
  const float* outW = (const float*)d_in[10];
  const float* outb = (const float*)d_in[11];
  float* out = (float*)d_out;

  cudaFuncSetAttribute(fused_kernel, cudaFuncAttributeMaxDynamicSharedMemorySize, FUSED_SMEM);

  prep_all<<<2177, 256>>>(enc, emb, Wih, Whh, bih, bhh, outW);
  fused_kernel<<<NCTA, NTHR, FUSED_SMEM>>>(tgt, outb, out);
}

// round 14
// speedup vs baseline: 2.1924x; 1.0849x over previous
#include <cuda_runtime.h>
#include <cuda_bf16.h>
#include <cuda_fp16.h>
#include <math.h>
#include <stdint.h>

#define Bn 256
#define Sn 141
#define Vn 1000
#define En 256
#define Hn 512
#define G4 2048   // 4*H
#define VP 1024   // padded vocab

#define NC_STEP 128         // recurrence CTAs (4 groups of 32)
#define NCTA    148         // persistent CTAs (1/SM)
#define NOUT    (Sn * 32)   // out tiles: per t, 2 m-tiles x 16 n-tiles
#define NTHR    512         // 16 warps

// ---------------- device scratch ----------------
__device__ float d_embgateP[(size_t)Vn * G4];     // [v][jp] fp32
__device__ float d_encgateP[(size_t)Bn * G4];     // [b][jp] fp32
__device__ __half d_Whh_h[(size_t)G4 * Hn];       // [jp][k] fp16 (single chain)
__device__ __half d_outW_h[(size_t)VP * Hn];      // [v][k] fp16 (single chain)
__device__ __half d_hs_f16[(size_t)Sn * Bn * Hn]; // [t][b][k] fp16

// sync state (reset by prep kernel each replay); 128B-spaced counters
__device__ unsigned d_countg[4 * 32];
__device__ unsigned d_senseg[4 * 32];
__device__ unsigned d_wq;

__device__ __forceinline__ int jperm(int j) {
  return ((j & 511) >> 4) * 64 + (j >> 9) * 16 + (j & 15);
}

// ---------------- PTX helpers (plain sm_80+ only) ----------------
__device__ __forceinline__ void cp16(uint32_t dst, const void* src) {
  asm volatile("cp.async.cg.shared.global [%0], [%1], 16;" :: "r"(dst), "l"(src));
}
__device__ __forceinline__ void cp_commit() { asm volatile("cp.async.commit_group;"); }
__device__ __forceinline__ void cp_wait0() { asm volatile("cp.async.wait_group 0;" ::: "memory"); }
__device__ __forceinline__ void cp_wait1() { asm volatile("cp.async.wait_group 1;" ::: "memory"); }

__device__ __forceinline__ void ldm4(uint32_t& r0, uint32_t& r1, uint32_t& r2, uint32_t& r3,
                                     uint32_t addr) {
  asm volatile("ldmatrix.sync.aligned.m8n8.x4.shared.b16 {%0,%1,%2,%3}, [%4];"
               : "=r"(r0), "=r"(r1), "=r"(r2), "=r"(r3) : "r"(addr));
}
__device__ __forceinline__ void mma_f16(float* d, const uint32_t* a, uint32_t b0, uint32_t b1) {
  asm volatile(
    "mma.sync.aligned.m16n8k16.row.col.f32.f16.f16.f32 "
    "{%0,%1,%2,%3}, {%4,%5,%6,%7}, {%8,%9}, {%0,%1,%2,%3};"
    : "+f"(d[0]), "+f"(d[1]), "+f"(d[2]), "+f"(d[3])
    : "r"(a[0]), "r"(a[1]), "r"(a[2]), "r"(a[3]), "r"(b0), "r"(b1));
}
__device__ __forceinline__ unsigned ld_acq(unsigned* p) {
  unsigned v;
  asm volatile("ld.acquire.gpu.u32 %0, [%1];" : "=r"(v) : "l"(p) : "memory");
  return v;
}

// ---------------- smem layout (recurrence) ----------------
#define BH_RES   0                     // 8 chunks x 8192 = 65536
#define A_FULL   65536                 // 8 chunks x 8192 = 65536 (whole A tile)
#define ADD_EMB  131072                // [64][64] f32 = 16384
#define ADD_ENC  147456                // 16384
#define GS_OFF   163840                // [64][68] f32 = 17408
#define GS_STRIDE 68
#define FUSED_SMEM 181248
// Out path (reuses offset 0): A fp16 128 rows + B 64 rows (24K/buffer)
#define STG_O    24576
#define OA_OFF   0
#define OB_HI    16384

// ---------------------------------------------------------------------------
// Merged prep kernel (unchanged, 256 threads)
// ---------------------------------------------------------------------------
#define MMA16(As, Bs) do {                                                       \
    _Pragma("unroll")                                                            \
    for (int kk = 0; kk < 16; ++kk) {                                            \
      float4 a = *(const float4*)&As[kk][ty * 4];                                \
      float4 b = *(const float4*)&Bs[kk][tx * 4];                                \
      acc[0][0] += a.x*b.x; acc[0][1] += a.x*b.y; acc[0][2] += a.x*b.z; acc[0][3] += a.x*b.w; \
      acc[1][0] += a.y*b.x; acc[1][1] += a.y*b.y; acc[1][2] += a.y*b.z; acc[1][3] += a.y*b.w; \
      acc[2][0] += a.z*b.x; acc[2][1] += a.z*b.y; acc[2][2] += a.z*b.z; acc[2][3] += a.z*b.w; \
      acc[3][0] += a.w*b.x; acc[3][1] += a.w*b.y; acc[3][2] += a.w*b.z; acc[3][3] += a.w*b.w; \
    } } while (0)

__global__ __launch_bounds__(256) void prep_all(
    const float* __restrict__ enc, const float* __restrict__ emb,
    const float* __restrict__ Wih, const float* __restrict__ Whh,
    const float* __restrict__ bih, const float* __restrict__ bhh,
    const float* __restrict__ outW) {
  __shared__ float As[16][64];
  __shared__ float Bs[16][64];
  int bid = blockIdx.x;
  int tid = threadIdx.x;

  if (bid < 640) {
    bool is_emb = bid < 512;
    int m0, n0;
    if (is_emb) { m0 = (bid & 15) * 64; n0 = (bid >> 4) * 64; }
    else        { int b2 = bid - 512; m0 = (b2 & 3) * 64; n0 = (b2 >> 2) * 64; }
    int tx = tid & 15, ty = tid >> 4;
    int lr = tid >> 2, lq = tid & 3;
    float acc[4][4] = {};
    for (int kc = 0; kc < En; kc += 16) {
      float4 av = make_float4(0.f, 0.f, 0.f, 0.f);
      float4 bv;
      if (is_emb) {
        if (m0 + lr < Vn)
          av = *(const float4*)(emb + (size_t)(m0 + lr) * En + kc + lq * 4);
        bv = *(const float4*)(Wih + (size_t)(n0 + lr) * (2 * En) + kc + lq * 4);
      } else {
        av = *(const float4*)(enc + (size_t)(m0 + lr) * En + kc + lq * 4);
        bv = *(const float4*)(Wih + (size_t)(n0 + lr) * (2 * En) + En + kc + lq * 4);
      }
      __syncthreads();
      As[lq*4+0][lr] = av.x; As[lq*4+1][lr] = av.y; As[lq*4+2][lr] = av.z; As[lq*4+3][lr] = av.w;
      Bs[lq*4+0][lr] = bv.x; Bs[lq*4+1][lr] = bv.y; Bs[lq*4+2][lr] = bv.z; Bs[lq*4+3][lr] = bv.w;
      __syncthreads();
      MMA16(As, Bs);
    }
#pragma unroll
    for (int ii = 0; ii < 4; ++ii) {
      int m = m0 + ty * 4 + ii;
      if (is_emb && m >= Vn) continue;
#pragma unroll
      for (int jj = 0; jj < 4; ++jj) {
        int n = n0 + tx * 4 + jj;
        if (is_emb)
          d_embgateP[(size_t)m * G4 + jperm(n)] = acc[ii][jj];
        else
          d_encgateP[(size_t)m * G4 + jperm(n)] = acc[ii][jj] + bih[n] + bhh[n];
      }
    }
  } else if (bid < 1664) {
    int i = (bid - 640) * 256 + tid;
    int e0 = i * 4;
    int j = e0 >> 9, k0 = e0 & 511;
    int jp = jperm(j);
    float4 x = *(const float4*)(Whh + e0);
    __half h[4];
    h[0] = __float2half_rn(x.x); h[1] = __float2half_rn(x.y);
    h[2] = __float2half_rn(x.z); h[3] = __float2half_rn(x.w);
    *(uint2*)(d_Whh_h + (size_t)jp * Hn + k0) = *(const uint2*)h;
  } else if (bid < 2176) {
    int i = (bid - 1664) * 256 + tid;
    int e0 = i * 4;
    int v = e0 >> 9;
    __half h[4];
    if (v < Vn) {
      float4 x = *(const float4*)(outW + e0);
      h[0] = __float2half_rn(x.x); h[1] = __float2half_rn(x.y);
      h[2] = __float2half_rn(x.z); h[3] = __float2half_rn(x.w);
    } else {
#pragma unroll
      for (int q = 0; q < 4; ++q) h[q] = __float2half_rn(0.f);
    }
    *(uint2*)(d_outW_h + e0) = *(const uint2*)h;
  } else {
    if (tid < 128) d_countg[tid] = 0;
    else if (tid < 256) d_senseg[tid - 128] = 0;
    if (tid == 0) d_wq = 0;
  }
}

// ============================================================================
// Recurrence: CTA tile 64x64, 16 warps, warp tile 16x16.
// Whole A tile resident per step; zero intra-GEMM barriers.
// ============================================================================
__device__ __forceinline__ void compute_chunk_r(
    float acc[2][4], uint32_t abase, uint32_t bhbase, int wm, int wn, int lane) {
  int lr = lane & 7;
  int sel = lane >> 3;
  int a_roff = (sel & 1) * 8;
  int a_koff = (sel & 2) * 8;          // bytes
  int b_koff = (sel & 1) * 16;         // bytes
  int b_roff = (sel & 2) * 4;
  uint32_t swm = (uint32_t)(lr * 16);

#pragma unroll
  for (int ks = 0; ks < 4; ++ks) {
    int kb = ks * 32;                  // bytes (16 k per ks)
    uint32_t a[4], bh[4];
    {
      int row = wm * 16 + lr + a_roff;
      uint32_t off = (uint32_t)row * 128 + (((uint32_t)(kb + a_koff)) ^ swm);
      ldm4(a[0], a[1], a[2], a[3], abase + off);
    }
    {
      int row = wn * 16 + lr + b_roff;
      uint32_t off = (uint32_t)row * 128 + (((uint32_t)(kb + b_koff)) ^ swm);
      ldm4(bh[0], bh[1], bh[2], bh[3], bhbase + off);
    }
    mma_f16(acc[0], a, bh[0], bh[1]);
    mma_f16(acc[1], a, bh[2], bh[3]);
  }
}

// ============================================================================
// Out tile: CTA tile 128x64, 16 warps, warp tile 32x16, 2-deep buffers.
// ============================================================================
#define LOADC_O(c, buf, AP, BhP)  do {                                           \
    int kc = (c) * 64;                                                           \
    uint32_t st = su + (buf) * STG_O;                                            \
    {                                                                            \
      int rowA = tid >> 2;                                                       \
      int sg0 = (tid & 3) * 2;                                                   \
      uint32_t swA = (uint32_t)(rowA & 7) * 16;                                  \
      _Pragma("unroll")                                                          \
      for (int q = 0; q < 2; ++q) {                                              \
        int sg = sg0 + q;                                                        \
        uint32_t so = (uint32_t)rowA * 128 + (((uint32_t)(sg * 16)) ^ swA);      \
        cp16(st + OA_OFF + so, (AP) + (size_t)rowA * Hn + kc + sg * 8);          \
      }                                                                          \
    }                                                                            \
    {                                                                            \
      int rB = tid >> 3;                                                         \
      int sg = tid & 7;                                                          \
      uint32_t swB = (uint32_t)(rB & 7) * 16;                                    \
      uint32_t so = (uint32_t)rB * 128 + (((uint32_t)(sg * 16)) ^ swB);          \
      cp16(st + OB_HI + so, (BhP) + (size_t)rB * Hn + kc + sg * 8);              \
    }                                                                            \
    cp_commit();                                                                 \
  } while (0)

__device__ __forceinline__ void compute_chunk_o(
    float accH[2][2][4], uint32_t su, int buf, int wm, int wn, int lane) {
  uint32_t base = su + buf * STG_O;
  int lr = lane & 7;
  int sel = lane >> 3;
  int a_roff = (sel & 1) * 8;
  int a_koff = (sel & 2) * 8;
  int b_koff = (sel & 1) * 16;
  int b_roff = (sel & 2) * 4;
  uint32_t swm = (uint32_t)(lr * 16);

#pragma unroll
  for (int ks = 0; ks < 4; ++ks) {
    int kb = ks * 32;
    uint32_t a[2][4], bh[4];
#pragma unroll
    for (int i = 0; i < 2; ++i) {
      int row = wm * 32 + i * 16 + lr + a_roff;
      uint32_t off = (uint32_t)row * 128 + (((uint32_t)(kb + a_koff)) ^ swm);
      ldm4(a[i][0], a[i][1], a[i][2], a[i][3], base + OA_OFF + off);
    }
    {
      int row = wn * 16 + lr + b_roff;
      uint32_t off = (uint32_t)row * 128 + (((uint32_t)(kb + b_koff)) ^ swm);
      ldm4(bh[0], bh[1], bh[2], bh[3], base + OB_HI + off);
    }
#pragma unroll
    for (int i = 0; i < 2; ++i) {
      mma_f16(accH[i][0], a[i], bh[0], bh[1]);
      mma_f16(accH[i][1], a[i], bh[2], bh[3]);
    }
  }
}

// ---------------------------------------------------------------------------
// Persistent fused kernel (512 threads, 16 warps).
// ---------------------------------------------------------------------------
__global__ __launch_bounds__(NTHR, 1) void fused_kernel(
    const int* __restrict__ tgt, const float* __restrict__ outb,
    float* __restrict__ out) {
  extern __shared__ __align__(1024) char smem[];
  __shared__ unsigned sidx;
  uint32_t su = (uint32_t)__cvta_generic_to_shared(smem);
  int tid = threadIdx.x;
  int lane = tid & 31, wid = tid >> 5;
  int wm = wid >> 2, wn = wid & 3;     // 4x4 warp grid

  if (blockIdx.x < NC_STEP) {
    // ========== recurrence: CTA tile 64 b-rows x 64 jp-cols ==========
    int mi = blockIdx.x >> 5, nblk = blockIdx.x & 31;
    int m0 = mi * 64, n0 = nblk * 64;
    unsigned* myCount = &d_countg[mi * 32];
    unsigned* mySense = &d_senseg[mi * 32];

    int ld_row = tid >> 3;             // 64 rows, 8 threads/row
    int ld_sg  = tid & 7;
    uint32_t ld_sw = (uint32_t)(ld_row & 7) * 16;
    uint32_t ld_so = (uint32_t)ld_row * 128 + (((uint32_t)(ld_sg * 16)) ^ ld_sw);

    // ---- resident loads: B (Whh tile, single chain) + enc addend ----
    {
      const __half* Bh = d_Whh_h + (size_t)n0 * Hn;
#pragma unroll
      for (int c = 0; c < 8; ++c)
        cp16(su + BH_RES + c * 8192 + ld_so, Bh + (size_t)ld_row * Hn + c * 64 + ld_sg * 8);
      int r = tid >> 3, sg0e = (tid & 7) * 2;
      const float* sc = d_encgateP + (size_t)(m0 + r) * G4 + n0;
      uint32_t dc = su + ADD_ENC + r * 256;
#pragma unroll
      for (int q = 0; q < 2; ++q)
        cp16(dc + (sg0e + q) * 16, sc + (sg0e + q) * 4);
      cp_commit();
      cp_wait0();
    }
    __syncthreads();

    int em_r = tid >> 3, em_sg = (tid & 7) * 2;
    int ep_m = tid >> 3, ep_k0 = (tid & 7) * 2;   // 2 cells per thread
    int ep_b = m0 + ep_m;
    int ep_kbase = nblk * 16 + ep_k0;
    const float* aE = (const float*)(smem + ADD_EMB) + ep_m * 64;
    const float* aC = (const float*)(smem + ADD_ENC) + ep_m * 64;
    float cpv[2] = {0.f, 0.f};

    for (int t = 0; t < Sn; ++t) {
      // issue ALL loads for this step: whole A tile + emb addend, one group
      if (t > 0) {
        const __half* A = d_hs_f16 + ((size_t)(t - 1) * Bn + m0) * Hn;
#pragma unroll
        for (int c = 0; c < 8; ++c)
          cp16(su + A_FULL + c * 8192 + ld_so, A + (size_t)ld_row * Hn + c * 64 + ld_sg * 8);
      }
      {
        int tok = tgt[(size_t)(m0 + em_r) * Sn + t];
        const float* se = d_embgateP + (size_t)tok * G4 + n0;
        uint32_t de = su + ADD_EMB + em_r * 256;
#pragma unroll
        for (int q = 0; q < 2; ++q)
          cp16(de + (em_sg + q) * 16, se + (em_sg + q) * 4);
      }
      cp_commit();
      cp_wait0();
      __syncthreads();

      if (t > 0) {
        float acc[2][4] = {};
#pragma unroll
        for (int c = 0; c < 8; ++c)
          compute_chunk_r(acc, su + A_FULL + c * 8192, su + BH_RES + c * 8192,
                          wm, wn, lane);
        // stage accums to Gs (disjoint region; no sync needed before writes)
        float* Gs = (float*)(smem + GS_OFF);
        int r0 = (lane >> 2), c0 = (lane & 3) * 2;
#pragma unroll
        for (int nt = 0; nt < 2; ++nt) {
          int row = wm * 16 + r0;
          int col = wn * 16 + nt * 8 + c0;
          Gs[row * GS_STRIDE + col]           = acc[nt][0];
          Gs[row * GS_STRIDE + col + 1]       = acc[nt][1];
          Gs[(row + 8) * GS_STRIDE + col]     = acc[nt][2];
          Gs[(row + 8) * GS_STRIDE + col + 1] = acc[nt][3];
        }
      }
      __syncthreads();

      // ---- fused LSTM elementwise: 2 cells/thread ----
      const float* Gs = (const float*)(smem + GS_OFF);
      __half hf[2];
#pragma unroll
      for (int q = 0; q < 2; ++q) {
        int kk = ep_k0 + q;
        float gi = aE[kk]      + aC[kk];
        float gf = aE[16 + kk] + aC[16 + kk];
        float gg = aE[32 + kk] + aC[32 + kk];
        float go = aE[48 + kk] + aC[48 + kk];
        if (t > 0) {
          gi += Gs[ep_m * GS_STRIDE + kk];
          gf += Gs[ep_m * GS_STRIDE + 16 + kk];
          gg += Gs[ep_m * GS_STRIDE + 32 + kk];
          go += Gs[ep_m * GS_STRIDE + 48 + kk];
        }
        float iv = 1.f / (1.f + expf(-gi));
        float fv = 1.f / (1.f + expf(-gf));
        float gv = tanhf(gg);
        float ov = 1.f / (1.f + expf(-go));
        float cc = fv * cpv[q] + iv * gv;
        cpv[q] = cc;
        hf[q] = __float2half_rn(ov * tanhf(cc));
      }
      *(uint32_t*)(d_hs_f16 + ((size_t)t * Bn + ep_b) * Hn + ep_kbase) =
          *(const uint32_t*)hf;

      // ---- per-group (32-CTA) barrier: atomic arrivals, sense-word wait ----
      __threadfence();
      __syncthreads();
      if (tid == 0) {
        unsigned old = atomicAdd(myCount, 1);
        if (old == 31) {
          atomicExch(myCount, 0);
          __threadfence();
          atomicAdd(mySense, 1);
        } else {
          while (ld_acq(mySense) < (unsigned)(t + 1)) { }
        }
      }
      __syncthreads();
    }
  }

  // ========== out-GEMM worker pool (all CTAs) ==========
  for (;;) {
    __syncthreads();
    if (tid == 0) sidx = atomicAdd(&d_wq, 1);
    __syncthreads();
    unsigned idx = sidx;
    if (idx >= NOUT) break;
    int t = idx >> 5;
    int sub = idx & 31;
    int mtile = sub >> 4;
    int m0g = t * Bn + mtile * 128;
    int n0 = (sub & 15) * 64;

    if (tid == 0) {
      unsigned* sA = &d_senseg[(mtile * 2) * 32];
      unsigned* sB = &d_senseg[(mtile * 2 + 1) * 32];
      while (ld_acq(sA) < (unsigned)(t + 1) || ld_acq(sB) < (unsigned)(t + 1))
        __nanosleep(128);
    }
    __syncthreads();

    const __half* A  = d_hs_f16 + (size_t)m0g * Hn;
    const __half* Bh = d_outW_h + (size_t)n0 * Hn;

    float accH[2][2][4] = {};
    LOADC_O(0, 0, A, Bh);
    LOADC_O(1, 1, A, Bh);
#pragma unroll 1
    for (int c = 0; c < 8; ++c) {
      if (c < 7) cp_wait1(); else cp_wait0();
      __syncthreads();
      compute_chunk_o(accH, su, c & 1, wm, wn, lane);
      __syncthreads();
      if (c + 2 < 8) LOADC_O(c + 2, c & 1, A, Bh);
    }

    int r0 = lane >> 2, c0 = (lane & 3) * 2;
#pragma unroll
    for (int nt = 0; nt < 2; ++nt) {
      int v = n0 + wn * 16 + nt * 8 + c0;
      if (v >= Vn) continue;
      float b0 = outb[v], b1 = outb[v + 1];
#pragma unroll
      for (int i = 0; i < 2; ++i) {
        int mrow = m0g + wm * 32 + i * 16 + r0;
#pragma unroll
        for (int h = 0; h < 2; ++h) {
          int m = mrow + h * 8;
          int bb = m & 255;
          float* dst = out + ((size_t)bb * Sn + t) * Vn + v;
          float2 o;
          o.x = accH[i][nt][h * 2 + 0] + b0;
          o.y = accH[i][nt][h * 2 + 1] + b1;
          *(float2*)dst = o;
        }
      }
    }
  }
}

extern "C" void kernel_launch(void* const* d_in, const int* in_sizes, int n_in,
                              void* d_out, int out_size) {
  const float* enc  = (const float*)d_in[0];
  const int*   tgt  = (const int*)  d_in[1];
  const float* emb  = (const float*)d_in[2];
  const float* Wih  = (const float*)d_in[3];
  const float* Whh  = (const float*)d_in[4];
  const float* bih  = (const float*)d_in[5];
  const float* bhh  = (const float*)d_in[6];
  // d_in[7..9] = attn_W, attn_b, v_w : dead (softmax over single source pos)
  const float* outW = (const float*)d_in[10];
  const float* outb = (const float*)d_in[11];
  float* out = (float*)d_out;

  cudaFuncSetAttribute(fused_kernel, cudaFuncAttributeMaxDynamicSharedMemorySize, FUSED_SMEM);

  prep_all<<<2177, 256>>>(enc, emb, Wih, Whh, bih, bhh, outW);
  fused_kernel<<<NCTA, NTHR, FUSED_SMEM>>>(tgt, outb, out);
}

// round 15
// speedup vs baseline: 2.2230x; 1.0139x over previous
#include <cuda_runtime.h>
#include <cuda_bf16.h>
#include <cuda_fp16.h>
#include <math.h>
#include <stdint.h>

#define Bn 256
#define Sn 141
#define Vn 1000
#define En 256
#define Hn 512
#define G4 2048   // 4*H
#define VP 1024   // padded vocab

#define NC_STEP 128         // recurrence CTAs (4 groups of 32)
#define NCTA    148         // persistent CTAs (1/SM)
#define NOUT    (Sn * 32)   // out tiles: per t, 2 m-tiles x 16 n-tiles
#define NTHR    512         // 16 warps

// ---------------- device scratch ----------------
__device__ float d_embgateP[(size_t)Vn * G4];     // [v][jp] fp32
__device__ float d_encgateP[(size_t)Bn * G4];     // [b][jp] fp32
__device__ __half d_Whh_h[(size_t)G4 * Hn];       // [jp][k] fp16 (single chain)
__device__ __half d_outW_h[(size_t)VP * Hn];      // [v][k] fp16 (single chain)
__device__ __half d_hs_f16[(size_t)Sn * Bn * Hn]; // [t][b][k] fp16

// sync state (reset by prep kernel each replay); 128B-spaced counters
__device__ unsigned d_countg[4 * 32];
__device__ unsigned d_senseg[4 * 32];
__device__ unsigned d_wq;

__device__ __forceinline__ int jperm(int j) {
  return ((j & 511) >> 4) * 64 + (j >> 9) * 16 + (j & 15);
}

// ---------------- PTX helpers (plain sm_80+ only) ----------------
__device__ __forceinline__ void cp16(uint32_t dst, const void* src) {
  asm volatile("cp.async.cg.shared.global [%0], [%1], 16;" :: "r"(dst), "l"(src));
}
__device__ __forceinline__ void cp_commit() { asm volatile("cp.async.commit_group;"); }
__device__ __forceinline__ void cp_wait0() { asm volatile("cp.async.wait_group 0;" ::: "memory"); }
__device__ __forceinline__ void cp_wait1() { asm volatile("cp.async.wait_group 1;" ::: "memory"); }

__device__ __forceinline__ void ldm4(uint32_t& r0, uint32_t& r1, uint32_t& r2, uint32_t& r3,
                                     uint32_t addr) {
  asm volatile("ldmatrix.sync.aligned.m8n8.x4.shared.b16 {%0,%1,%2,%3}, [%4];"
               : "=r"(r0), "=r"(r1), "=r"(r2), "=r"(r3) : "r"(addr));
}
__device__ __forceinline__ void mma_f16(float* d, const uint32_t* a, uint32_t b0, uint32_t b1) {
  asm volatile(
    "mma.sync.aligned.m16n8k16.row.col.f32.f16.f16.f32 "
    "{%0,%1,%2,%3}, {%4,%5,%6,%7}, {%8,%9}, {%0,%1,%2,%3};"
    : "+f"(d[0]), "+f"(d[1]), "+f"(d[2]), "+f"(d[3])
    : "r"(a[0]), "r"(a[1]), "r"(a[2]), "r"(a[3]), "r"(b0), "r"(b1));
}
__device__ __forceinline__ unsigned ld_acq(unsigned* p) {
  unsigned v;
  asm volatile("ld.acquire.gpu.u32 %0, [%1];" : "=r"(v) : "l"(p) : "memory");
  return v;
}

// ---------------- smem layout (recurrence) ----------------
#define BH_RES   0                     // 8 chunks x 8192 = 65536
#define A_FULL   65536                 // 8 chunks x 8192 = 65536 (whole A tile)
#define ADD_EMB  131072                // 2 x [64][64] f32 = 32768 (double buffer)
#define ADD_ENC  163840                // 16384
#define GS_OFF   180224                // [64][68] f32 = 17408
#define GS_STRIDE 68
#define FUSED_SMEM 197632
// Out path (reuses offset 0): A fp16 128 rows + B 64 rows (24K/buffer)
#define STG_O    24576
#define OA_OFF   0
#define OB_HI    16384

// ---------------------------------------------------------------------------
// Merged prep kernel (unchanged, 256 threads)
// ---------------------------------------------------------------------------
#define MMA16(As, Bs) do {                                                       \
    _Pragma("unroll")                                                            \
    for (int kk = 0; kk < 16; ++kk) {                                            \
      float4 a = *(const float4*)&As[kk][ty * 4];                                \
      float4 b = *(const float4*)&Bs[kk][tx * 4];                                \
      acc[0][0] += a.x*b.x; acc[0][1] += a.x*b.y; acc[0][2] += a.x*b.z; acc[0][3] += a.x*b.w; \
      acc[1][0] += a.y*b.x; acc[1][1] += a.y*b.y; acc[1][2] += a.y*b.z; acc[1][3] += a.y*b.w; \
      acc[2][0] += a.z*b.x; acc[2][1] += a.z*b.y; acc[2][2] += a.z*b.z; acc[2][3] += a.z*b.w; \
      acc[3][0] += a.w*b.x; acc[3][1] += a.w*b.y; acc[3][2] += a.w*b.z; acc[3][3] += a.w*b.w; \
    } } while (0)

__global__ __launch_bounds__(256) void prep_all(
    const float* __restrict__ enc, const float* __restrict__ emb,
    const float* __restrict__ Wih, const float* __restrict__ Whh,
    const float* __restrict__ bih, const float* __restrict__ bhh,
    const float* __restrict__ outW) {
  __shared__ float As[16][64];
  __shared__ float Bs[16][64];
  int bid = blockIdx.x;
  int tid = threadIdx.x;

  if (bid < 640) {
    bool is_emb = bid < 512;
    int m0, n0;
    if (is_emb) { m0 = (bid & 15) * 64; n0 = (bid >> 4) * 64; }
    else        { int b2 = bid - 512; m0 = (b2 & 3) * 64; n0 = (b2 >> 2) * 64; }
    int tx = tid & 15, ty = tid >> 4;
    int lr = tid >> 2, lq = tid & 3;
    float acc[4][4] = {};
    for (int kc = 0; kc < En; kc += 16) {
      float4 av = make_float4(0.f, 0.f, 0.f, 0.f);
      float4 bv;
      if (is_emb) {
        if (m0 + lr < Vn)
          av = *(const float4*)(emb + (size_t)(m0 + lr) * En + kc + lq * 4);
        bv = *(const float4*)(Wih + (size_t)(n0 + lr) * (2 * En) + kc + lq * 4);
      } else {
        av = *(const float4*)(enc + (size_t)(m0 + lr) * En + kc + lq * 4);
        bv = *(const float4*)(Wih + (size_t)(n0 + lr) * (2 * En) + En + kc + lq * 4);
      }
      __syncthreads();
      As[lq*4+0][lr] = av.x; As[lq*4+1][lr] = av.y; As[lq*4+2][lr] = av.z; As[lq*4+3][lr] = av.w;
      Bs[lq*4+0][lr] = bv.x; Bs[lq*4+1][lr] = bv.y; Bs[lq*4+2][lr] = bv.z; Bs[lq*4+3][lr] = bv.w;
      __syncthreads();
      MMA16(As, Bs);
    }
#pragma unroll
    for (int ii = 0; ii < 4; ++ii) {
      int m = m0 + ty * 4 + ii;
      if (is_emb && m >= Vn) continue;
#pragma unroll
      for (int jj = 0; jj < 4; ++jj) {
        int n = n0 + tx * 4 + jj;
        if (is_emb)
          d_embgateP[(size_t)m * G4 + jperm(n)] = acc[ii][jj];
        else
          d_encgateP[(size_t)m * G4 + jperm(n)] = acc[ii][jj] + bih[n] + bhh[n];
      }
    }
  } else if (bid < 1664) {
    int i = (bid - 640) * 256 + tid;
    int e0 = i * 4;
    int j = e0 >> 9, k0 = e0 & 511;
    int jp = jperm(j);
    float4 x = *(const float4*)(Whh + e0);
    __half h[4];
    h[0] = __float2half_rn(x.x); h[1] = __float2half_rn(x.y);
    h[2] = __float2half_rn(x.z); h[3] = __float2half_rn(x.w);
    *(uint2*)(d_Whh_h + (size_t)jp * Hn + k0) = *(const uint2*)h;
  } else if (bid < 2176) {
    int i = (bid - 1664) * 256 + tid;
    int e0 = i * 4;
    int v = e0 >> 9;
    __half h[4];
    if (v < Vn) {
      float4 x = *(const float4*)(outW + e0);
      h[0] = __float2half_rn(x.x); h[1] = __float2half_rn(x.y);
      h[2] = __float2half_rn(x.z); h[3] = __float2half_rn(x.w);
    } else {
#pragma unroll
      for (int q = 0; q < 4; ++q) h[q] = __float2half_rn(0.f);
    }
    *(uint2*)(d_outW_h + e0) = *(const uint2*)h;
  } else {
    if (tid < 128) d_countg[tid] = 0;
    else if (tid < 256) d_senseg[tid - 128] = 0;
    if (tid == 0) d_wq = 0;
  }
}

// ============================================================================
// Recurrence: CTA tile 64x64, 16 warps, warp tile 16x16.
// Whole A tile resident per step; half-pipelined loads (2 waits/step).
// ============================================================================
__device__ __forceinline__ void compute_chunk_r(
    float acc[2][4], uint32_t abase, uint32_t bhbase, int wm, int wn, int lane) {
  int lr = lane & 7;
  int sel = lane >> 3;
  int a_roff = (sel & 1) * 8;
  int a_koff = (sel & 2) * 8;          // bytes
  int b_koff = (sel & 1) * 16;         // bytes
  int b_roff = (sel & 2) * 4;
  uint32_t swm = (uint32_t)(lr * 16);

#pragma unroll
  for (int ks = 0; ks < 4; ++ks) {
    int kb = ks * 32;                  // bytes (16 k per ks)
    uint32_t a[4], bh[4];
    {
      int row = wm * 16 + lr + a_roff;
      uint32_t off = (uint32_t)row * 128 + (((uint32_t)(kb + a_koff)) ^ swm);
      ldm4(a[0], a[1], a[2], a[3], abase + off);
    }
    {
      int row = wn * 16 + lr + b_roff;
      uint32_t off = (uint32_t)row * 128 + (((uint32_t)(kb + b_koff)) ^ swm);
      ldm4(bh[0], bh[1], bh[2], bh[3], bhbase + off);
    }
    mma_f16(acc[0], a, bh[0], bh[1]);
    mma_f16(acc[1], a, bh[2], bh[3]);
  }
}

// ============================================================================
// Out tile: CTA tile 128x64, 16 warps, warp tile 32x16, 2-deep buffers.
// ============================================================================
#define LOADC_O(c, buf, AP, BhP)  do {                                           \
    int kc = (c) * 64;                                                           \
    uint32_t st = su + (buf) * STG_O;                                            \
    {                                                                            \
      int rowA = tid >> 2;                                                       \
      int sg0 = (tid & 3) * 2;                                                   \
      uint32_t swA = (uint32_t)(rowA & 7) * 16;                                  \
      _Pragma("unroll")                                                          \
      for (int q = 0; q < 2; ++q) {                                              \
        int sg = sg0 + q;                                                        \
        uint32_t so = (uint32_t)rowA * 128 + (((uint32_t)(sg * 16)) ^ swA);      \
        cp16(st + OA_OFF + so, (AP) + (size_t)rowA * Hn + kc + sg * 8);          \
      }                                                                          \
    }                                                                            \
    {                                                                            \
      int rB = tid >> 3;                                                         \
      int sg = tid & 7;                                                          \
      uint32_t swB = (uint32_t)(rB & 7) * 16;                                    \
      uint32_t so = (uint32_t)rB * 128 + (((uint32_t)(sg * 16)) ^ swB);          \
      cp16(st + OB_HI + so, (BhP) + (size_t)rB * Hn + kc + sg * 8);              \
    }                                                                            \
    cp_commit();                                                                 \
  } while (0)

__device__ __forceinline__ void compute_chunk_o(
    float accH[2][2][4], uint32_t su, int buf, int wm, int wn, int lane) {
  uint32_t base = su + buf * STG_O;
  int lr = lane & 7;
  int sel = lane >> 3;
  int a_roff = (sel & 1) * 8;
  int a_koff = (sel & 2) * 8;
  int b_koff = (sel & 1) * 16;
  int b_roff = (sel & 2) * 4;
  uint32_t swm = (uint32_t)(lr * 16);

#pragma unroll
  for (int ks = 0; ks < 4; ++ks) {
    int kb = ks * 32;
    uint32_t a[2][4], bh[4];
#pragma unroll
    for (int i = 0; i < 2; ++i) {
      int row = wm * 32 + i * 16 + lr + a_roff;
      uint32_t off = (uint32_t)row * 128 + (((uint32_t)(kb + a_koff)) ^ swm);
      ldm4(a[i][0], a[i][1], a[i][2], a[i][3], base + OA_OFF + off);
    }
    {
      int row = wn * 16 + lr + b_roff;
      uint32_t off = (uint32_t)row * 128 + (((uint32_t)(kb + b_koff)) ^ swm);
      ldm4(bh[0], bh[1], bh[2], bh[3], base + OB_HI + off);
    }
#pragma unroll
    for (int i = 0; i < 2; ++i) {
      mma_f16(accH[i][0], a[i], bh[0], bh[1]);
      mma_f16(accH[i][1], a[i], bh[2], bh[3]);
    }
  }
}

// ---------------------------------------------------------------------------
// Persistent fused kernel (512 threads, 16 warps).
// ---------------------------------------------------------------------------
__global__ __launch_bounds__(NTHR, 1) void fused_kernel(
    const int* __restrict__ tgt, const float* __restrict__ outb,
    float* __restrict__ out) {
  extern __shared__ __align__(1024) char smem[];
  __shared__ unsigned sidx;
  uint32_t su = (uint32_t)__cvta_generic_to_shared(smem);
  int tid = threadIdx.x;
  int lane = tid & 31, wid = tid >> 5;
  int wm = wid >> 2, wn = wid & 3;     // 4x4 warp grid

  if (blockIdx.x < NC_STEP) {
    // ========== recurrence: CTA tile 64 b-rows x 64 jp-cols ==========
    int mi = blockIdx.x >> 5, nblk = blockIdx.x & 31;
    int m0 = mi * 64, n0 = nblk * 64;
    unsigned* myCount = &d_countg[mi * 32];
    unsigned* mySense = &d_senseg[mi * 32];

    int ld_row = tid >> 3;             // 64 rows, 8 threads/row
    int ld_sg  = tid & 7;
    uint32_t ld_sw = (uint32_t)(ld_row & 7) * 16;
    uint32_t ld_so = (uint32_t)ld_row * 128 + (((uint32_t)(ld_sg * 16)) ^ ld_sw);

    int em_r = tid >> 3, em_sg = (tid & 7) * 2;

    // ---- resident loads: B (Whh tile) + enc addend + emb(0) into buf 0 ----
    {
      const __half* Bh = d_Whh_h + (size_t)n0 * Hn;
#pragma unroll
      for (int c = 0; c < 8; ++c)
        cp16(su + BH_RES + c * 8192 + ld_so, Bh + (size_t)ld_row * Hn + c * 64 + ld_sg * 8);
      int r = tid >> 3, sg0e = (tid & 7) * 2;
      const float* sc = d_encgateP + (size_t)(m0 + r) * G4 + n0;
      uint32_t dc = su + ADD_ENC + r * 256;
#pragma unroll
      for (int q = 0; q < 2; ++q)
        cp16(dc + (sg0e + q) * 16, sc + (sg0e + q) * 4);
      // emb(0) into buffer 0
      int tok0 = tgt[(size_t)(m0 + em_r) * Sn + 0];
      const float* se = d_embgateP + (size_t)tok0 * G4 + n0;
      uint32_t de = su + ADD_EMB + em_r * 256;
#pragma unroll
      for (int q = 0; q < 2; ++q)
        cp16(de + (em_sg + q) * 16, se + (em_sg + q) * 4);
      cp_commit();
      cp_wait0();
    }
    __syncthreads();

    int ep_m = tid >> 3, ep_k0 = (tid & 7) * 2;   // 2 cells per thread
    int ep_b = m0 + ep_m;
    int ep_kbase = nblk * 16 + ep_k0;
    const float* aC = (const float*)(smem + ADD_ENC) + ep_m * 64;
    float cpv[2] = {0.f, 0.f};

    for (int t = 0; t < Sn; ++t) {
      const __half* A = d_hs_f16 + ((size_t)(t - 1) * Bn + m0) * Hn;
      // Group 1: A chunks 0-3
      if (t > 0) {
#pragma unroll
        for (int c = 0; c < 4; ++c)
          cp16(su + A_FULL + c * 8192 + ld_so, A + (size_t)ld_row * Hn + c * 64 + ld_sg * 8);
        cp_commit();
      }
      // Group 2: A chunks 4-7 + emb(t+1) prefetch into buffer (t+1)&1
      {
        if (t > 0) {
#pragma unroll
          for (int c = 4; c < 8; ++c)
            cp16(su + A_FULL + c * 8192 + ld_so, A + (size_t)ld_row * Hn + c * 64 + ld_sg * 8);
        }
        if (t + 1 < Sn) {
          int tok = tgt[(size_t)(m0 + em_r) * Sn + (t + 1)];
          const float* se = d_embgateP + (size_t)tok * G4 + n0;
          uint32_t de = su + ADD_EMB + ((t + 1) & 1) * 16384 + em_r * 256;
#pragma unroll
          for (int q = 0; q < 2; ++q)
            cp16(de + (em_sg + q) * 16, se + (em_sg + q) * 4);
        }
        cp_commit();
      }

      if (t > 0) {
        float acc[2][4] = {};
        cp_wait1();                    // group 1 (A chunks 0-3) landed
        __syncthreads();
#pragma unroll
        for (int c = 0; c < 4; ++c)
          compute_chunk_r(acc, su + A_FULL + c * 8192, su + BH_RES + c * 8192,
                          wm, wn, lane);
        cp_wait0();                    // group 2 (A 4-7 + emb(t+1)) landed
        __syncthreads();
#pragma unroll
        for (int c = 4; c < 8; ++c)
          compute_chunk_r(acc, su + A_FULL + c * 8192, su + BH_RES + c * 8192,
                          wm, wn, lane);
        // stage accums to Gs (disjoint region; no sync needed before writes)
        float* Gs = (float*)(smem + GS_OFF);
        int r0 = (lane >> 2), c0 = (lane & 3) * 2;
#pragma unroll
        for (int nt = 0; nt < 2; ++nt) {
          int row = wm * 16 + r0;
          int col = wn * 16 + nt * 8 + c0;
          Gs[row * GS_STRIDE + col]           = acc[nt][0];
          Gs[row * GS_STRIDE + col + 1]       = acc[nt][1];
          Gs[(row + 8) * GS_STRIDE + col]     = acc[nt][2];
          Gs[(row + 8) * GS_STRIDE + col + 1] = acc[nt][3];
        }
      }
      __syncthreads();

      // ---- fused LSTM elementwise: 2 cells/thread ----
      const float* Gs = (const float*)(smem + GS_OFF);
      const float* aE = (const float*)(smem + ADD_EMB + (t & 1) * 16384) + ep_m * 64;
      __half hf[2];
#pragma unroll
      for (int q = 0; q < 2; ++q) {
        int kk = ep_k0 + q;
        float gi = aE[kk]      + aC[kk];
        float gf = aE[16 + kk] + aC[16 + kk];
        float gg = aE[32 + kk] + aC[32 + kk];
        float go = aE[48 + kk] + aC[48 + kk];
        if (t > 0) {
          gi += Gs[ep_m * GS_STRIDE + kk];
          gf += Gs[ep_m * GS_STRIDE + 16 + kk];
          gg += Gs[ep_m * GS_STRIDE + 32 + kk];
          go += Gs[ep_m * GS_STRIDE + 48 + kk];
        }
        float iv = 1.f / (1.f + expf(-gi));
        float fv = 1.f / (1.f + expf(-gf));
        float gv = tanhf(gg);
        float ov = 1.f / (1.f + expf(-go));
        float cc = fv * cpv[q] + iv * gv;
        cpv[q] = cc;
        hf[q] = __float2half_rn(ov * tanhf(cc));
      }
      *(uint32_t*)(d_hs_f16 + ((size_t)t * Bn + ep_b) * Hn + ep_kbase) =
          *(const uint32_t*)hf;

      // ---- per-group (32-CTA) barrier: atomic arrivals, sense-word wait ----
      __threadfence();
      __syncthreads();
      if (tid == 0) {
        unsigned old = atomicAdd(myCount, 1);
        if (old == 31) {
          atomicExch(myCount, 0);
          __threadfence();
          atomicAdd(mySense, 1);
        } else {
          while (ld_acq(mySense) < (unsigned)(t + 1)) { }
        }
      }
      __syncthreads();
    }
  }

  // ========== out-GEMM worker pool (all CTAs) ==========
  for (;;) {
    __syncthreads();
    if (tid == 0) sidx = atomicAdd(&d_wq, 1);
    __syncthreads();
    unsigned idx = sidx;
    if (idx >= NOUT) break;
    int t = idx >> 5;
    int sub = idx & 31;
    int mtile = sub >> 4;
    int m0g = t * Bn + mtile * 128;
    int n0 = (sub & 15) * 64;

    if (tid == 0) {
      unsigned* sA = &d_senseg[(mtile * 2) * 32];
      unsigned* sB = &d_senseg[(mtile * 2 + 1) * 32];
      while (ld_acq(sA) < (unsigned)(t + 1) || ld_acq(sB) < (unsigned)(t + 1))
        __nanosleep(128);
    }
    __syncthreads();

    const __half* A  = d_hs_f16 + (size_t)m0g * Hn;
    const __half* Bh = d_outW_h + (size_t)n0 * Hn;

    float accH[2][2][4] = {};
    LOADC_O(0, 0, A, Bh);
    LOADC_O(1, 1, A, Bh);
#pragma unroll 1
    for (int c = 0; c < 8; ++c) {
      if (c < 7) cp_wait1(); else cp_wait0();
      __syncthreads();
      compute_chunk_o(accH, su, c & 1, wm, wn, lane);
      __syncthreads();
      if (c + 2 < 8) LOADC_O(c + 2, c & 1, A, Bh);
    }

    int r0 = lane >> 2, c0 = (lane & 3) * 2;
#pragma unroll
    for (int nt = 0; nt < 2; ++nt) {
      int v = n0 + wn * 16 + nt * 8 + c0;
      if (v >= Vn) continue;
      float b0 = outb[v], b1 = outb[v + 1];
#pragma unroll
      for (int i = 0; i < 2; ++i) {
        int mrow = m0g + wm * 32 + i * 16 + r0;
#pragma unroll
        for (int h = 0; h < 2; ++h) {
          int m = mrow + h * 8;
          int bb = m & 255;
          float* dst = out + ((size_t)bb * Sn + t) * Vn + v;
          float2 o;
          o.x = accH[i][nt][h * 2 + 0] + b0;
          o.y = accH[i][nt][h * 2 + 1] + b1;
          *(float2*)dst = o;
        }
      }
    }
  }
}

extern "C" void kernel_launch(void* const* d_in, const int* in_sizes, int n_in,
                              void* d_out, int out_size) {
  const float* enc  = (const float*)d_in[0];
  const int*   tgt  = (const int*)  d_in[1];
  const float* emb  = (const float*)d_in[2];
  const float* Wih  = (const float*)d_in[3];
  const float* Whh  = (const float*)d_in[4];
  const float* bih  = (const float*)d_in[5];
  const float* bhh  = (const float*)d_in[6];
  // d_in[7..9] = attn_W, attn_b, v_w : dead (softmax over single source pos)
  const float* outW = (const float*)d_in[10];
  const float* outb = (const float*)d_in[11];
  float* out = (float*)d_out;

  cudaFuncSetAttribute(fused_kernel, cudaFuncAttributeMaxDynamicSharedMemorySize, FUSED_SMEM);

  prep_all<<<2177, 256>>>(enc, emb, Wih, Whh, bih, bhh, outW);
  fused_kernel<<<NCTA, NTHR, FUSED_SMEM>>>(tgt, outb, out);
}